// round 2
// baseline (speedup 1.0000x reference)
#include <cuda_runtime.h>
#include <math.h>

#define Mm 3
#define Bb 32
#define Ss 256
#define Dd 768
#define Hh 1024
#define NPAIR 6
#define LNEPS 1e-5f
// 1/sqrt(768)
#define SCALE 0.036084391824351615f

__constant__ int c_pi[NPAIR] = {0,0,1,1,2,2};
__constant__ int c_pj[NPAIR] = {1,2,0,2,0,1};

// ---------------- scratch (__device__ globals; no runtime allocation) ------------
__device__ float g_wmu[Mm][Dd], g_wlv[Mm][Dd], g_wpq[Mm][Dd];
__device__ float g_cmu[Mm], g_clv[Mm], g_cpq[Mm];
__device__ float g_wpk[Mm][Mm][Dd];
__device__ float g_cpk[Mm][Mm];
__device__ float g_Q0[Mm][Bb][Dd];
__device__ float g_qkvec[Mm][Mm][Bb][Dd];
__device__ float g_qbk[Mm][Mm][Bb];
__device__ float g_mu[Mm][Bb][Ss], g_lv[Mm][Bb][Ss], g_pqb[Mm][Bb][Ss];
__device__ float g_kd[Mm][Mm][Bb][Ss];
__device__ float g_wf[Mm][Mm][Bb][Dd];
__device__ float g_agg[Mm][Bb][Dd];
__device__ float g_E[Mm][Bb][Dd], g_G[Mm][Bb][Dd];
__device__ float g_C[Mm][Bb][Dd];
__device__ float g_kl;

__device__ __forceinline__ float warp_sum(float v){
    #pragma unroll
    for(int o=16;o>0;o>>=1) v += __shfl_down_sync(0xffffffffu, v, o);
    return v;
}
__device__ __forceinline__ float sigmoidf(float x){ return 1.f/(1.f+expf(-x)); }

// -------- kernel 0: zero accumulators (graph-replay safe) --------
__global__ void k_zero(){ g_kl = 0.f; }

// -------- kernel 1: composite weight vectors --------
// w_mu[m,d] = sum_e Wq[m,d,e]*mu_w[m,e]  (same for lv, pq);  w_pk[i,j,d] = sum_e Wk[j,d,e]*pgk_w[i,e]
__global__ void k_comp(const float* __restrict__ Wq, const float* __restrict__ Wk,
                       const float* __restrict__ mu_w, const float* __restrict__ lv_w,
                       const float* __restrict__ pgq_w, const float* __restrict__ pgk_w){
    int wid = (blockIdx.x*blockDim.x + threadIdx.x)>>5;
    int lane = threadIdx.x & 31;
    if (wid < Mm*Dd){
        int m = wid/Dd, d = wid%Dd;
        const float* row = Wq + ((size_t)m*Dd + d)*Dd;
        float a=0.f,b=0.f,c=0.f;
        for(int e=lane;e<Dd;e+=32){
            float w = row[e];
            a += w*mu_w[m*Dd+e]; b += w*lv_w[m*Dd+e]; c += w*pgq_w[m*Dd+e];
        }
        a=warp_sum(a); b=warp_sum(b); c=warp_sum(c);
        if(!lane){ g_wmu[m][d]=a; g_wlv[m][d]=b; g_wpq[m][d]=c; }
    } else {
        int w2 = wid - Mm*Dd;
        if (w2 >= Mm*Mm*Dd) return;
        int i = w2/(Mm*Dd); int rem = w2%(Mm*Dd); int j = rem/Dd; int d = rem%Dd;
        const float* row = Wk + ((size_t)j*Dd + d)*Dd;
        float a=0.f;
        for(int e=lane;e<Dd;e+=32) a += row[e]*pgk_w[i*Dd+e];
        a=warp_sum(a);
        if(!lane) g_wpk[i][j][d]=a;
    }
}

// -------- kernel 2: scalar constants --------
__global__ void k_consts(const float* __restrict__ bq, const float* __restrict__ bk,
                         const float* __restrict__ mu_w, const float* __restrict__ mu_b,
                         const float* __restrict__ lv_w, const float* __restrict__ lv_b,
                         const float* __restrict__ pgq_w, const float* __restrict__ pgq_b,
                         const float* __restrict__ pgk_w, const float* __restrict__ pgk_b){
    int t = threadIdx.x>>5, lane = threadIdx.x&31;
    if (t < 9){
        int m = t/3, which = t%3;
        const float* wv = (which==0)? mu_w : (which==1)? lv_w : pgq_w;
        float a=0.f;
        for(int e=lane;e<Dd;e+=32) a += bq[m*Dd+e]*wv[m*Dd+e];
        a=warp_sum(a);
        if(!lane){
            if(which==0) g_cmu[m]=a+mu_b[m];
            else if(which==1) g_clv[m]=a+lv_b[m];
            else g_cpq[m]=a+pgq_b[m];
        }
    } else if (t < 18){
        int q=t-9; int i=q/3, j=q%3;
        float a=0.f;
        for(int e=lane;e<Dd;e+=32) a += bk[j*Dd+e]*pgk_w[i*Dd+e];
        a=warp_sum(a);
        if(!lane) g_cpk[i][j]=a+pgk_b[i];
    }
}

// -------- kernel 3: Q0[i,b,:] = feats[i,b,0,:] @ Wq[i] + bq[i]  (tiled mini-GEMM) --------
__global__ void k_q0(const float* __restrict__ feats, const float* __restrict__ Wq,
                     const float* __restrict__ bq){
    __shared__ float sh[32][64];
    int i = blockIdx.x/12, et = blockIdx.x%12;
    int tx = threadIdx.x%64, ty = threadIdx.x/64;
    int e = et*64 + tx;
    float acc[8];
    #pragma unroll
    for(int r=0;r<8;r++) acc[r]=bq[i*Dd+e];
    for(int dc=0; dc<Dd; dc+=64){
        __syncthreads();
        for(int q=threadIdx.x;q<32*64;q+=256){
            int bb=q/64, dd=q%64;
            sh[bb][dd] = feats[(((size_t)i*Bb+bb)*Ss)*Dd + dc+dd];
        }
        __syncthreads();
        for(int d=0; d<64; d++){
            float w = Wq[((size_t)i*Dd + dc+d)*Dd + e];
            #pragma unroll
            for(int r=0;r<8;r++) acc[r] += sh[ty+r*4][d]*w;
        }
    }
    #pragma unroll
    for(int r=0;r<8;r++) g_Q0[i][ty+r*4][e]=acc[r];
}

// -------- kernel 4: qkvec[i,j,b,d] = sum_e Wk[j,d,e]*Q0[i,b,e]  (shared-tiled GEMM, Wk read once) --------
__global__ void k_qkvec(const float* __restrict__ Wk){
    __shared__ float shq[64][64];
    __shared__ float shw[64][65];
    int j = blockIdx.x/12, dt = blockIdx.x%12;
    int i0 = (j==0)?1:0, i1 = (j==2)?1:2;
    int tx = threadIdx.x%64, ty = threadIdx.x/64;
    int d = dt*64 + tx;
    float acc[16];
    #pragma unroll
    for(int r=0;r<16;r++) acc[r]=0.f;
    for(int ec=0; ec<Dd; ec+=64){
        __syncthreads();
        for(int q=threadIdx.x;q<64*64;q+=256){
            int rr=q/64, cc=q%64;
            int ii=(rr<32)?i0:i1; int bb=rr&31;
            shq[rr][cc] = g_Q0[ii][bb][ec+cc];
            shw[rr][cc] = Wk[((size_t)j*Dd + dt*64 + rr)*Dd + ec + cc];
        }
        __syncthreads();
        for(int ee=0; ee<64; ee++){
            float w = shw[tx][ee];
            #pragma unroll
            for(int r=0;r<16;r++) acc[r] += shq[ty+r*4][ee]*w;
        }
    }
    #pragma unroll
    for(int r=0;r<16;r++){
        int vv = ty + r*4; int ii=(vv<32)?i0:i1; int bb=vv&31;
        g_qkvec[ii][j][bb][d]=acc[r];
    }
}

// -------- kernel 5: qbk[i,j,b] = bk[j] . Q0[i,b]  --------
__global__ void k_qbk(const float* __restrict__ bk){
    int p = blockIdx.x; int i=c_pi[p], j=c_pj[p];
    int wid=threadIdx.x>>5, lane=threadIdx.x&31;
    for(int b=wid;b<Bb;b+=8){
        float a=0.f;
        for(int e=lane;e<Dd;e+=32) a += bk[j*Dd+e]*g_Q0[i][b][e];
        a=warp_sum(a);
        if(!lane) g_qbk[i][j][b]=a;
    }
}

// -------- kernel 6: row stats (mu, lv, pqb, kd) + kl reduction; single feats pass --------
__global__ void k_rowstats(const float* __restrict__ feats){
    __shared__ float sw[5][Dd];
    __shared__ float skl[8];
    int m = blockIdx.x/Bb, b = blockIdx.x%Bb;
    int i0=(m==0)?1:0, i1=(m==2)?1:2;
    for(int d=threadIdx.x; d<Dd; d+=256){
        sw[0][d]=g_wmu[m][d]; sw[1][d]=g_wlv[m][d]; sw[2][d]=g_wpq[m][d];
        sw[3][d]=g_wpk[i0][m][d]; sw[4][d]=g_wpk[i1][m][d];
    }
    __syncthreads();
    int wid=threadIdx.x>>5, lane=threadIdx.x&31;
    float klacc=0.f;
    const float* base = feats + ((size_t)m*Bb+b)*Ss*Dd;
    for(int s=wid; s<Ss; s+=8){
        const float* fr = base + (size_t)s*Dd;
        float a0=0,a1=0,a2=0,a3=0,a4=0;
        for(int d=lane; d<Dd; d+=32){
            float f=fr[d];
            a0+=f*sw[0][d]; a1+=f*sw[1][d]; a2+=f*sw[2][d]; a3+=f*sw[3][d]; a4+=f*sw[4][d];
        }
        a0=warp_sum(a0); a1=warp_sum(a1); a2=warp_sum(a2); a3=warp_sum(a3); a4=warp_sum(a4);
        if(!lane){
            float mu=a0+g_cmu[m], lv=a1+g_clv[m];
            g_mu[m][b][s]=mu; g_lv[m][b][s]=lv;
            g_pqb[m][b][s]=a2+g_cpq[m];
            g_kd[i0][m][b][s]=a3+g_cpk[i0][m];
            g_kd[i1][m][b][s]=a4+g_cpk[i1][m];
            klacc += 1.f + lv - mu*mu - expf(lv);
        }
    }
    klacc = warp_sum(klacc);
    if(!lane) skl[wid]=klacc;
    __syncthreads();
    if(threadIdx.x==0){
        float t=0.f;
        #pragma unroll
        for(int w=0;w<8;w++) t+=skl[w];
        atomicAdd(&g_kl, t);
    }
}

// -------- kernel 7: per-(pair,b) attention row q=0: logits -> gates -> softmax -> weighted feats sum --------
__global__ void k_attn(const float* __restrict__ feats, const float* __restrict__ eps,
                       const float* __restrict__ dyn){
    __shared__ float sq[Dd];
    __shared__ float sA[Ss];
    __shared__ float sred[8];
    __shared__ float s_scalar;
    __shared__ float s_pq;
    int blk=blockIdx.x; int p=blk/Bb, b=blk%Bb;
    int i=c_pi[p], j=c_pj[p];
    int cnt = (j<i)? j : j-1;
    float dynv = dyn[0];
    for(int d=threadIdx.x; d<Dd; d+=256) sq[d]=g_qkvec[i][j][b][d];
    if(threadIdx.x==0){
        float mu0=g_mu[i][b][0], lv0=g_lv[i][b][0];
        float e0 = eps[(((size_t)i*(Mm-1)+cnt)*Bb + b)*Ss + 0];
        float g0 = sigmoidf(mu0 + dynv*expf(0.5f*lv0)*e0);
        s_pq = sigmoidf(g_pqb[i][b][0]) * g0;
    }
    __syncthreads();
    int wid=threadIdx.x>>5, lane=threadIdx.x&31;
    const float* ftile = feats + (((size_t)j*Bb+b)*Ss)*Dd;
    float qbk = g_qbk[i][j][b];
    for(int k=wid; k<Ss; k+=8){
        const float* fr = ftile + (size_t)k*Dd;
        float a=0.f;
        for(int d=lane; d<Dd; d+=32) a += fr[d]*sq[d];
        a=warp_sum(a);
        if(!lane){
            float mu=g_mu[i][b][k], lv=g_lv[i][b][k];
            float e = eps[(((size_t)i*(Mm-1)+cnt)*Bb + b)*Ss + k];
            float gk = sigmoidf(mu + dynv*expf(0.5f*lv)*e);
            float pk = sigmoidf(g_kd[i][j][b][k]) * gk;
            sA[k] = (a + qbk) * SCALE * s_pq * pk;
        }
    }
    __syncthreads();
    // softmax over 256 logits, thread tid owns k=tid
    float v = sA[threadIdx.x];
    float mx = v;
    #pragma unroll
    for(int o=16;o>0;o>>=1) mx = fmaxf(mx, __shfl_xor_sync(0xffffffffu, mx, o));
    if(!lane) sred[wid]=mx;
    __syncthreads();
    if(threadIdx.x==0){
        float t=sred[0];
        #pragma unroll
        for(int w=1;w<8;w++) t=fmaxf(t,sred[w]);
        s_scalar=t;
    }
    __syncthreads();
    float ex = expf(v - s_scalar);
    float sm = ex;
    #pragma unroll
    for(int o=16;o>0;o>>=1) sm += __shfl_xor_sync(0xffffffffu, sm, o);
    if(!lane) sred[wid]=sm;
    __syncthreads();
    if(threadIdx.x==0){
        float t=0.f;
        #pragma unroll
        for(int w=0;w<8;w++) t+=sred[w];
        s_scalar=t;
    }
    __syncthreads();
    sA[threadIdx.x] = ex / s_scalar;   // softmax weights W[k]
    __syncthreads();
    // wf[d] = sum_k W[k]*feats[j,b,k,d]
    for(int d=threadIdx.x; d<Dd; d+=256){
        float acc=0.f;
        for(int k=0;k<Ss;k++) acc += sA[k]*ftile[(size_t)k*Dd + d];
        g_wf[i][j][b][d]=acc;
    }
}

// -------- kernel 8: agg[i,b,e] = sum_{j!=i} (wf[i,j,b,:] @ Wv[j] + bv[j]) --------
__global__ void k_agg(const float* __restrict__ Wv, const float* __restrict__ bv){
    __shared__ float sh[2][32][64];
    int i = blockIdx.x/12, et = blockIdx.x%12;
    int tx = threadIdx.x%64, ty = threadIdx.x/64;
    int e = et*64 + tx;
    int j0=(i==0)?1:0, j1=(i==2)?1:2;
    float acc[8];
    #pragma unroll
    for(int r=0;r<8;r++) acc[r]=bv[j0*Dd+e]+bv[j1*Dd+e];
    for(int dc=0; dc<Dd; dc+=64){
        __syncthreads();
        for(int q=threadIdx.x;q<2*32*64;q+=256){
            int jj=q/(32*64); int rr=q%(32*64); int bb=rr/64; int dd=rr%64;
            int jidx = jj? j1 : j0;
            sh[jj][bb][dd]=g_wf[i][jidx][bb][dc+dd];
        }
        __syncthreads();
        for(int d=0; d<64; d++){
            float w0 = Wv[((size_t)j0*Dd + dc+d)*Dd + e];
            float w1 = Wv[((size_t)j1*Dd + dc+d)*Dd + e];
            #pragma unroll
            for(int r=0;r<8;r++){
                int bb=ty+r*4;
                acc[r] += sh[0][bb][d]*w0 + sh[1][bb][d]*w1;
            }
        }
    }
    #pragma unroll
    for(int r=0;r<8;r++) g_agg[i][ty+r*4][e]=acc[r];
}

// -------- kernel 9: E = relu(agg@WE+b), G = relu(agg@Wh+b + Q0@Wqc+b) --------
__global__ void k_eg(const float* __restrict__ WE, const float* __restrict__ WEb,
                     const float* __restrict__ Wh, const float* __restrict__ Whb,
                     const float* __restrict__ Wqc, const float* __restrict__ Wqcb){
    __shared__ float sa[32][64];
    __shared__ float sq[32][64];
    int i = blockIdx.x/12, et = blockIdx.x%12;
    int tx = threadIdx.x%64, ty = threadIdx.x/64;
    int e = et*64 + tx;
    float aE[8], aG[8];
    #pragma unroll
    for(int r=0;r<8;r++){ aE[r]=WEb[i*Dd+e]; aG[r]=Whb[i*Dd+e]+Wqcb[i*Dd+e]; }
    for(int dc=0; dc<Dd; dc+=64){
        __syncthreads();
        for(int q=threadIdx.x;q<32*64;q+=256){
            int bb=q/64, dd=q%64;
            sa[bb][dd]=g_agg[i][bb][dc+dd];
            sq[bb][dd]=g_Q0[i][bb][dc+dd];
        }
        __syncthreads();
        for(int d=0; d<64; d++){
            size_t off = ((size_t)i*Dd + dc+d)*Dd + e;
            float we=WE[off], wh=Wh[off], wq=Wqc[off];
            #pragma unroll
            for(int r=0;r<8;r++){
                int bb=ty+r*4;
                aE[r] += sa[bb][d]*we;
                aG[r] += sa[bb][d]*wh + sq[bb][d]*wq;
            }
        }
    }
    #pragma unroll
    for(int r=0;r<8;r++){
        int bb=ty+r*4;
        g_E[i][bb][e]=fmaxf(aE[r],0.f);
        g_G[i][bb][e]=fmaxf(aG[r],0.f);
    }
}

__device__ __forceinline__ float block_sum256(float v, float* sred){
    v = warp_sum(v);
    int wid=threadIdx.x>>5, lane=threadIdx.x&31;
    if(!lane) sred[wid]=v;
    __syncthreads();
    float t = (threadIdx.x<8)? sred[threadIdx.x] : 0.f;
    if(threadIdx.x<32){
        #pragma unroll
        for(int o=16;o>0;o>>=1) t += __shfl_xor_sync(0xffffffffu,t,o);
        if(threadIdx.x==0) sred[0]=t;
    }
    __syncthreads();
    float r = sred[0];
    __syncthreads();
    return r;
}

// -------- kernel 10: C = LN(E)*LN(G) --------
__global__ void k_lnprod(const float* __restrict__ lnEg, const float* __restrict__ lnEb,
                         const float* __restrict__ lnGg, const float* __restrict__ lnGb){
    __shared__ float sred[8];
    int i = blockIdx.x/Bb, b = blockIdx.x%Bb;
    float se=0.f, se2=0.f, sg=0.f, sg2=0.f;
    for(int d=threadIdx.x; d<Dd; d+=256){
        float ev=g_E[i][b][d], gv=g_G[i][b][d];
        se+=ev; se2+=ev*ev; sg+=gv; sg2+=gv*gv;
    }
    se  = block_sum256(se , sred);
    se2 = block_sum256(se2, sred);
    sg  = block_sum256(sg , sred);
    sg2 = block_sum256(sg2, sred);
    float mE = se/(float)Dd,  vE = se2/(float)Dd - mE*mE;
    float mG = sg/(float)Dd,  vG = sg2/(float)Dd - mG*mG;
    float rE = rsqrtf(vE + LNEPS), rG = rsqrtf(vG + LNEPS);
    for(int d=threadIdx.x; d<Dd; d+=256){
        float nE = (g_E[i][b][d]-mE)*rE*lnEg[i*Dd+d] + lnEb[i*Dd+d];
        float nG = (g_G[i][b][d]-mG)*rG*lnGg[i*Dd+d] + lnGb[i*Dd+d];
        g_C[i][b][d] = nE*nG;
    }
}

// -------- kernel 11: out[b,h] = fused[b,:] @ out_w + out_b --------
__global__ void k_out(const float* __restrict__ out_w, const float* __restrict__ out_b,
                      float* __restrict__ dout){
    __shared__ float sf[32][64];
    int ht = blockIdx.x;
    int tx = threadIdx.x%64, ty = threadIdx.x/64;
    int h = ht*64 + tx;
    float acc[8];
    #pragma unroll
    for(int r=0;r<8;r++) acc[r]=out_b[h];
    for(int cc=0; cc<Mm*Dd; cc+=64){
        __syncthreads();
        for(int q=threadIdx.x;q<32*64;q+=256){
            int bb=q/64, d2=q%64;
            int c=cc+d2; int ii=c/Dd; int dd=c%Dd;
            sf[bb][d2]=g_C[ii][bb][dd];
        }
        __syncthreads();
        for(int d=0; d<64; d++){
            float w = out_w[((size_t)(cc+d))*Hh + h];
            #pragma unroll
            for(int r=0;r<8;r++) acc[r]+=sf[ty+r*4][d]*w;
        }
    }
    #pragma unroll
    for(int r=0;r<8;r++) dout[(size_t)(ty+r*4)*Hh + h]=acc[r];
}

// -------- kernel 12: kl scalar --------
__global__ void k_klw(float* __restrict__ dout, int write_kl){
    if(write_kl) dout[Bb*Hh] = -0.5f*(float)(Mm-1)*g_kl;
}

extern "C" void kernel_launch(void* const* d_in, const int* in_sizes, int n_in,
                              void* d_out, int out_size) {
    const float* feats = (const float*)d_in[0];
    const float* Wq    = (const float*)d_in[1];
    const float* bq    = (const float*)d_in[2];
    const float* Wk    = (const float*)d_in[3];
    const float* bk    = (const float*)d_in[4];
    const float* Wv    = (const float*)d_in[5];
    const float* bv    = (const float*)d_in[6];
    const float* pgq_w = (const float*)d_in[7];
    const float* pgq_b = (const float*)d_in[8];
    const float* pgk_w = (const float*)d_in[9];
    const float* pgk_b = (const float*)d_in[10];
    const float* mu_w  = (const float*)d_in[11];
    const float* mu_b  = (const float*)d_in[12];
    const float* lv_w  = (const float*)d_in[13];
    const float* lv_b  = (const float*)d_in[14];
    const float* dyn   = (const float*)d_in[15];
    const float* WE_w  = (const float*)d_in[16];
    const float* WE_b  = (const float*)d_in[17];
    const float* Wh_w  = (const float*)d_in[18];
    const float* Wh_b  = (const float*)d_in[19];
    const float* Wqc_w = (const float*)d_in[20];
    const float* Wqc_b = (const float*)d_in[21];
    const float* lnE_g = (const float*)d_in[22];
    const float* lnE_b = (const float*)d_in[23];
    const float* lnG_g = (const float*)d_in[24];
    const float* lnG_b = (const float*)d_in[25];
    const float* out_w = (const float*)d_in[26];
    const float* out_b = (const float*)d_in[27];
    const float* eps   = (const float*)d_in[28];
    float* dout = (float*)d_out;

    k_zero<<<1,1>>>();
    {
        int warps = Mm*Dd + Mm*Mm*Dd;            // 9216
        int blocks = (warps + 7)/8;              // 8 warps/block
        k_comp<<<blocks,256>>>(Wq, Wk, mu_w, lv_w, pgq_w, pgk_w);
    }
    k_consts<<<1,576>>>(bq, bk, mu_w, mu_b, lv_w, lv_b, pgq_w, pgq_b, pgk_w, pgk_b);
    k_q0<<<Mm*12,256>>>(feats, Wq, bq);
    k_qkvec<<<Mm*12,256>>>(Wk);
    k_qbk<<<NPAIR,256>>>(bk);
    k_rowstats<<<Mm*Bb,256>>>(feats);
    k_attn<<<NPAIR*Bb,256>>>(feats, eps, dyn);
    k_agg<<<Mm*12,256>>>(Wv, bv);
    k_eg<<<Mm*12,256>>>(WE_w, WE_b, Wh_w, Wh_b, Wqc_w, Wqc_b);
    k_lnprod<<<Mm*Bb,256>>>(lnE_g, lnE_b, lnG_g, lnG_b);
    k_out<<<Hh/64,256>>>(out_w, out_b, dout);
    k_klw<<<1,1>>>(dout, (out_size > Bb*Hh) ? 1 : 0);
}

// round 3
// speedup vs baseline: 3.2754x; 3.2754x over previous
#include <cuda_runtime.h>
#include <math.h>

#define Mm 3
#define Bb 32
#define Ss 256
#define Dd 768
#define D4 192
#define Hh 1024
#define NPAIR 6
#define LNEPS 1e-5f
#define SCALE 0.036084391824351615f

// ---------------- scratch (__device__ globals; no runtime allocation) ------------
__device__ __align__(16) float g_wmu[Mm][Dd], g_wlv[Mm][Dd], g_wpq[Mm][Dd];
__device__ float g_cmu[Mm], g_clv[Mm], g_cpq[Mm];
__device__ __align__(16) float g_wpk[Mm][Mm][Dd];
__device__ float g_cpk[Mm][Mm];
__device__ __align__(16) float g_Q0[Mm][Bb][Dd];          // atomic accum
__device__ __align__(16) float g_qkvec[Mm][Mm][Bb][Dd];   // atomic accum
__device__ float g_qbk[Mm][Mm][Bb];
__device__ float g_mu[Mm][Bb][Ss], g_lv[Mm][Bb][Ss], g_pqb[Mm][Bb][Ss];
__device__ float g_kd[Mm][Mm][Bb][Ss];
__device__ float g_W[Mm][Mm][Bb][Ss];                     // softmax weights
__device__ __align__(16) float g_wf[Mm][Mm][Bb][Dd];
__device__ __align__(16) float g_agg[Mm][Bb][Dd];         // atomic accum
__device__ __align__(16) float g_E[Mm][Bb][Dd], g_G[Mm][Bb][Dd]; // atomic accum (pre-relu)
__device__ __align__(16) float g_C[Mm][Bb][Dd];
__device__ float g_kl;

__device__ __forceinline__ float warp_sum(float v){
    #pragma unroll
    for(int o=16;o>0;o>>=1) v += __shfl_down_sync(0xffffffffu, v, o);
    return v;
}
__device__ __forceinline__ float sigmoidf(float x){ return 1.f/(1.f+expf(-x)); }
__device__ __forceinline__ float dot4(float4 a, float4 b){
    return a.x*b.x + a.y*b.y + a.z*b.z + a.w*b.w;
}

// -------- kernel 0: zero all atomic accumulators (graph-replay safe) --------
__global__ void k_zero(){
    int tid = blockIdx.x*blockDim.x + threadIdx.x;
    int stride = gridDim.x*blockDim.x;
    float* p;
    p = &g_Q0[0][0][0];
    for(int i=tid;i<Mm*Bb*Dd;i+=stride) p[i]=0.f;
    p = &g_qkvec[0][0][0][0];
    for(int i=tid;i<Mm*Mm*Bb*Dd;i+=stride) p[i]=0.f;
    p = &g_agg[0][0][0];
    for(int i=tid;i<Mm*Bb*Dd;i+=stride) p[i]=0.f;
    p = &g_E[0][0][0];
    for(int i=tid;i<Mm*Bb*Dd;i+=stride) p[i]=0.f;
    p = &g_G[0][0][0];
    for(int i=tid;i<Mm*Bb*Dd;i+=stride) p[i]=0.f;
    if(tid==0) g_kl=0.f;
}

// -------- kernel 1: composite weight vectors (Wq read 1x, Wk read 1x) --------
__global__ void k_comp(const float* __restrict__ Wq, const float* __restrict__ Wk,
                       const float* __restrict__ mu_w, const float* __restrict__ lv_w,
                       const float* __restrict__ pgq_w, const float* __restrict__ pgk_w){
    int wid = (blockIdx.x*blockDim.x + threadIdx.x)>>5;
    int lane = threadIdx.x & 31;
    if (wid < Mm*Dd){
        int m = wid/Dd, d = wid%Dd;
        const float4* row = (const float4*)(Wq + ((size_t)m*Dd + d)*Dd);
        const float4* v0 = (const float4*)(mu_w + m*Dd);
        const float4* v1 = (const float4*)(lv_w + m*Dd);
        const float4* v2 = (const float4*)(pgq_w + m*Dd);
        float a=0.f,b=0.f,c=0.f;
        for(int e=lane;e<D4;e+=32){
            float4 w = row[e];
            a += dot4(w,v0[e]); b += dot4(w,v1[e]); c += dot4(w,v2[e]);
        }
        a=warp_sum(a); b=warp_sum(b); c=warp_sum(c);
        if(!lane){ g_wmu[m][d]=a; g_wlv[m][d]=b; g_wpq[m][d]=c; }
    } else {
        int w2 = wid - Mm*Dd;
        if (w2 >= Mm*Dd) return;
        int j = w2/Dd, d = w2%Dd;
        const float4* row = (const float4*)(Wk + ((size_t)j*Dd + d)*Dd);
        const float4* v0 = (const float4*)(pgk_w + 0*Dd);
        const float4* v1 = (const float4*)(pgk_w + 1*Dd);
        const float4* v2 = (const float4*)(pgk_w + 2*Dd);
        float a=0.f,b=0.f,c=0.f;
        for(int e=lane;e<D4;e+=32){
            float4 w = row[e];
            a += dot4(w,v0[e]); b += dot4(w,v1[e]); c += dot4(w,v2[e]);
        }
        a=warp_sum(a); b=warp_sum(b); c=warp_sum(c);
        if(!lane){ g_wpk[0][j][d]=a; g_wpk[1][j][d]=b; g_wpk[2][j][d]=c; }
    }
}

// -------- kernel 2: scalar constants --------
__global__ void k_consts(const float* __restrict__ bq, const float* __restrict__ bk,
                         const float* __restrict__ mu_w, const float* __restrict__ mu_b,
                         const float* __restrict__ lv_w, const float* __restrict__ lv_b,
                         const float* __restrict__ pgq_w, const float* __restrict__ pgq_b,
                         const float* __restrict__ pgk_w, const float* __restrict__ pgk_b){
    int t = threadIdx.x>>5, lane = threadIdx.x&31;
    if (t < 9){
        int m = t/3, which = t%3;
        const float* wv = (which==0)? mu_w : (which==1)? lv_w : pgq_w;
        float a=0.f;
        for(int e=lane;e<Dd;e+=32) a += bq[m*Dd+e]*wv[m*Dd+e];
        a=warp_sum(a);
        if(!lane){
            if(which==0) g_cmu[m]=a+mu_b[m];
            else if(which==1) g_clv[m]=a+lv_b[m];
            else g_cpq[m]=a+pgq_b[m];
        }
    } else if (t < 18){
        int q=t-9; int i=q/3, j=q%3;
        float a=0.f;
        for(int e=lane;e<Dd;e+=32) a += bk[j*Dd+e]*pgk_w[i*Dd+e];
        a=warp_sum(a);
        if(!lane) g_cpk[i][j]=a+pgk_b[i];
    }
}

// -------- kernel 3: Q0 += feats[:,:,0,:] @ Wq (split-K, 144 blocks) --------
__global__ void k_q0(const float* __restrict__ feats, const float* __restrict__ Wq,
                     const float* __restrict__ bq){
    __shared__ float sh[32][64];
    int blk = blockIdx.x;
    int i  = blk/48;
    int et = (blk/4)%12;
    int kc = blk%4;
    int tx = threadIdx.x%64, ty = threadIdx.x/64;
    int e = et*64 + tx;
    float acc[8];
    float binit = (kc==0)? bq[i*Dd+e] : 0.f;
    #pragma unroll
    for(int r=0;r<8;r++) acc[r]=binit;
    for(int dc=kc*192; dc<kc*192+192; dc+=64){
        __syncthreads();
        for(int q=threadIdx.x;q<512;q+=256){
            int bb=q/16, dd4=q%16;
            ((float4*)sh[bb])[dd4] =
                ((const float4*)(feats + (((size_t)i*Bb+bb)*Ss)*Dd + dc))[dd4];
        }
        __syncthreads();
        for(int d=0; d<64; d++){
            float w = Wq[((size_t)i*Dd + dc+d)*Dd + e];
            #pragma unroll
            for(int r=0;r<8;r++) acc[r] += sh[ty+r*4][d]*w;
        }
    }
    #pragma unroll
    for(int r=0;r<8;r++) atomicAdd(&g_Q0[i][ty+r*4][e], acc[r]);
}

// -------- kernel 4: qkvec[i,j,b,d] += sum_e Wk[j,d,e]*Q0[i,b,e] (split-K) --------
__global__ void k_qkvec(const float* __restrict__ Wk){
    __shared__ float shq[64][64];
    __shared__ float shw[64][65];
    int blk = blockIdx.x;
    int j  = blk/48;
    int dt = (blk/4)%12;
    int kc = blk%4;
    int i0 = (j==0)?1:0, i1 = (j==2)?1:2;
    int tx = threadIdx.x%64, ty = threadIdx.x/64;
    int d = dt*64 + tx;
    float acc[16];
    #pragma unroll
    for(int r=0;r<16;r++) acc[r]=0.f;
    for(int ec=kc*192; ec<kc*192+192; ec+=64){
        __syncthreads();
        for(int q=threadIdx.x;q<64*64;q+=256){
            int rr=q/64, cc=q%64;
            int ii=(rr<32)?i0:i1; int bb=rr&31;
            shq[rr][cc] = g_Q0[ii][bb][ec+cc];
            shw[rr][cc] = Wk[((size_t)j*Dd + dt*64 + rr)*Dd + ec + cc];
        }
        __syncthreads();
        for(int ee=0; ee<64; ee++){
            float w = shw[tx][ee];
            #pragma unroll
            for(int r=0;r<16;r++) acc[r] += shq[ty+r*4][ee]*w;
        }
    }
    #pragma unroll
    for(int r=0;r<16;r++){
        int vv = ty + r*4; int ii=(vv<32)?i0:i1; int bb=vv&31;
        atomicAdd(&g_qkvec[ii][j][bb][d], acc[r]);
    }
}

// -------- kernel 5: qbk[i,j,b] = bk[j] . Q0[i,b] --------
__global__ void k_qbk(const float* __restrict__ bk){
    const int pi[NPAIR]={0,0,1,1,2,2}, pj[NPAIR]={1,2,0,2,0,1};
    int p = blockIdx.x; int i=pi[p], j=pj[p];
    int wid=threadIdx.x>>5, lane=threadIdx.x&31;
    for(int b=wid;b<Bb;b+=8){
        float a=0.f;
        for(int e=lane;e<Dd;e+=32) a += bk[j*Dd+e]*g_Q0[i][b][e];
        a=warp_sum(a);
        if(!lane) g_qbk[i][j][b]=a;
    }
}

// -------- kernel 6: row stats + kl, s-split (384 blocks), float4 --------
__global__ void k_rowstats(const float* __restrict__ feats){
    __shared__ float4 sw4[5][D4];
    __shared__ float skl[8];
    int blk = blockIdx.x;
    int m  = blk/(Bb*4);
    int b  = (blk/4)%Bb;
    int sc = blk%4;
    int i0=(m==0)?1:0, i1=(m==2)?1:2;
    for(int d=threadIdx.x; d<D4; d+=256){
        sw4[0][d]=((const float4*)g_wmu[m])[d];
        sw4[1][d]=((const float4*)g_wlv[m])[d];
        sw4[2][d]=((const float4*)g_wpq[m])[d];
        sw4[3][d]=((const float4*)g_wpk[i0][m])[d];
        sw4[4][d]=((const float4*)g_wpk[i1][m])[d];
    }
    __syncthreads();
    int wid=threadIdx.x>>5, lane=threadIdx.x&31;
    float klacc=0.f;
    const float* base = feats + ((size_t)m*Bb+b)*Ss*Dd;
    for(int s=sc*64+wid; s<sc*64+64; s+=8){
        const float4* fr = (const float4*)(base + (size_t)s*Dd);
        float a0=0,a1=0,a2=0,a3=0,a4=0;
        for(int d=lane; d<D4; d+=32){
            float4 f=fr[d];
            a0+=dot4(f,sw4[0][d]); a1+=dot4(f,sw4[1][d]); a2+=dot4(f,sw4[2][d]);
            a3+=dot4(f,sw4[3][d]); a4+=dot4(f,sw4[4][d]);
        }
        a0=warp_sum(a0); a1=warp_sum(a1); a2=warp_sum(a2); a3=warp_sum(a3); a4=warp_sum(a4);
        if(!lane){
            float mu=a0+g_cmu[m], lv=a1+g_clv[m];
            g_mu[m][b][s]=mu; g_lv[m][b][s]=lv;
            g_pqb[m][b][s]=a2+g_cpq[m];
            g_kd[i0][m][b][s]=a3+g_cpk[i0][m];
            g_kd[i1][m][b][s]=a4+g_cpk[i1][m];
            klacc += 1.f + lv - mu*mu - expf(lv);
        }
    }
    klacc = warp_sum(klacc);
    if(!lane) skl[wid]=klacc;
    __syncthreads();
    if(threadIdx.x==0){
        float t=0.f;
        #pragma unroll
        for(int w=0;w<8;w++) t+=skl[w];
        atomicAdd(&g_kl, t);
    }
}

// -------- kernel 7a: dots + gates + softmax for BOTH i of each (j,b); feats read 1x --------
__global__ void k_attn1(const float* __restrict__ feats, const float* __restrict__ eps,
                        const float* __restrict__ dyn){
    __shared__ float4 sq0[D4], sq1[D4];
    __shared__ float sA0[Ss], sA1[Ss];
    __shared__ float sred[8];
    __shared__ float spq0, spq1, sscal;
    int j = blockIdx.x/Bb, b = blockIdx.x%Bb;
    int i0=(j==0)?1:0, i1=(j==2)?1:2;
    int cnt0 = (j<i0)? j : j-1;
    int cnt1 = (j<i1)? j : j-1;
    for(int d=threadIdx.x; d<D4; d+=256){
        sq0[d]=((const float4*)g_qkvec[i0][j][b])[d];
        sq1[d]=((const float4*)g_qkvec[i1][j][b])[d];
    }
    __syncthreads();
    int wid=threadIdx.x>>5, lane=threadIdx.x&31;
    const float* ftile = feats + (((size_t)j*Bb+b)*Ss)*Dd;
    float qbk0 = g_qbk[i0][j][b], qbk1 = g_qbk[i1][j][b];
    for(int k=wid; k<Ss; k+=8){
        const float4* fr = (const float4*)(ftile + (size_t)k*Dd);
        float a0=0.f, a1=0.f;
        for(int d=lane; d<D4; d+=32){
            float4 f=fr[d];
            a0 += dot4(f,sq0[d]); a1 += dot4(f,sq1[d]);
        }
        a0=warp_sum(a0); a1=warp_sum(a1);
        if(!lane){ sA0[k]=a0+qbk0; sA1[k]=a1+qbk1; }
    }
    __syncthreads();
    // thread k computes gates and logits for both pairs
    int k = threadIdx.x;
    float dynv = dyn[0];
    float mu0=g_mu[i0][b][k], lv0=g_lv[i0][b][k];
    float e0 = eps[(((size_t)i0*(Mm-1)+cnt0)*Bb + b)*Ss + k];
    float gk0 = sigmoidf(mu0 + dynv*expf(0.5f*lv0)*e0);
    float pk0 = sigmoidf(g_kd[i0][j][b][k]) * gk0;
    float mu1=g_mu[i1][b][k], lv1=g_lv[i1][b][k];
    float e1 = eps[(((size_t)i1*(Mm-1)+cnt1)*Bb + b)*Ss + k];
    float gk1 = sigmoidf(mu1 + dynv*expf(0.5f*lv1)*e1);
    float pk1 = sigmoidf(g_kd[i1][j][b][k]) * gk1;
    if(k==0){
        spq0 = sigmoidf(g_pqb[i0][b][0]) * gk0;
        spq1 = sigmoidf(g_pqb[i1][b][0]) * gk1;
    }
    __syncthreads();
    float l0 = sA0[k]*SCALE*spq0*pk0;
    float l1 = sA1[k]*SCALE*spq1*pk1;
    // softmax for pair 0
    {
        float mx=l0;
        #pragma unroll
        for(int o=16;o>0;o>>=1) mx=fmaxf(mx,__shfl_xor_sync(0xffffffffu,mx,o));
        if(!lane) sred[wid]=mx;
        __syncthreads();
        if(threadIdx.x==0){ float t=sred[0];
            #pragma unroll
            for(int w=1;w<8;w++) t=fmaxf(t,sred[w]); sscal=t; }
        __syncthreads();
        float ex=expf(l0-sscal);
        float sm=ex;
        #pragma unroll
        for(int o=16;o>0;o>>=1) sm+=__shfl_xor_sync(0xffffffffu,sm,o);
        if(!lane) sred[wid]=sm;
        __syncthreads();
        if(threadIdx.x==0){ float t=0.f;
            #pragma unroll
            for(int w=0;w<8;w++) t+=sred[w]; sscal=t; }
        __syncthreads();
        g_W[i0][j][b][k]=ex/sscal;
        __syncthreads();
    }
    // softmax for pair 1
    {
        float mx=l1;
        #pragma unroll
        for(int o=16;o>0;o>>=1) mx=fmaxf(mx,__shfl_xor_sync(0xffffffffu,mx,o));
        if(!lane) sred[wid]=mx;
        __syncthreads();
        if(threadIdx.x==0){ float t=sred[0];
            #pragma unroll
            for(int w=1;w<8;w++) t=fmaxf(t,sred[w]); sscal=t; }
        __syncthreads();
        float ex=expf(l1-sscal);
        float sm=ex;
        #pragma unroll
        for(int o=16;o>0;o>>=1) sm+=__shfl_xor_sync(0xffffffffu,sm,o);
        if(!lane) sred[wid]=sm;
        __syncthreads();
        if(threadIdx.x==0){ float t=0.f;
            #pragma unroll
            for(int w=0;w<8;w++) t+=sred[w]; sscal=t; }
        __syncthreads();
        g_W[i1][j][b][k]=ex/sscal;
    }
}

// -------- kernel 7b: weighted feats sums for BOTH i; d-split (288 blocks) --------
__global__ void k_attn2(const float* __restrict__ feats){
    __shared__ float w0[Ss], w1[Ss];
    int blk = blockIdx.x;
    int j  = blk/(Bb*3);
    int b  = (blk/3)%Bb;
    int dc = blk%3;
    int i0=(j==0)?1:0, i1=(j==2)?1:2;
    if(threadIdx.x < Ss){
        w0[threadIdx.x]=g_W[i0][j][b][threadIdx.x];
        w1[threadIdx.x]=g_W[i1][j][b][threadIdx.x];
    }
    __syncthreads();
    int d = dc*256 + threadIdx.x;
    const float* ftile = feats + (((size_t)j*Bb+b)*Ss)*Dd;
    float acc0=0.f, acc1=0.f;
    #pragma unroll 4
    for(int k=0;k<Ss;k++){
        float f = ftile[(size_t)k*Dd + d];
        acc0 += w0[k]*f; acc1 += w1[k]*f;
    }
    g_wf[i0][j][b][d]=acc0;
    g_wf[i1][j][b][d]=acc1;
}

// -------- kernel 8: agg[i] += sum_j wf[i,j] @ Wv[j] (split-K, 144 blocks) --------
__global__ void k_agg(const float* __restrict__ Wv, const float* __restrict__ bv){
    __shared__ float sh[2][32][64];
    int blk = blockIdx.x;
    int i  = blk/48;
    int et = (blk/4)%12;
    int kc = blk%4;
    int tx = threadIdx.x%64, ty = threadIdx.x/64;
    int e = et*64 + tx;
    int j0=(i==0)?1:0, j1=(i==2)?1:2;
    float acc[8];
    float binit = (kc==0)? (bv[j0*Dd+e]+bv[j1*Dd+e]) : 0.f;
    #pragma unroll
    for(int r=0;r<8;r++) acc[r]=binit;
    for(int dc=kc*192; dc<kc*192+192; dc+=64){
        __syncthreads();
        for(int q=threadIdx.x;q<2*32*64;q+=256){
            int jj=q/(32*64); int rr=q%(32*64); int bb=rr/64; int dd=rr%64;
            int jidx = jj? j1 : j0;
            sh[jj][bb][dd]=g_wf[i][jidx][bb][dc+dd];
        }
        __syncthreads();
        for(int d=0; d<64; d++){
            float v0 = Wv[((size_t)j0*Dd + dc+d)*Dd + e];
            float v1 = Wv[((size_t)j1*Dd + dc+d)*Dd + e];
            #pragma unroll
            for(int r=0;r<8;r++){
                int bb=ty+r*4;
                acc[r] += sh[0][bb][d]*v0 + sh[1][bb][d]*v1;
            }
        }
    }
    #pragma unroll
    for(int r=0;r<8;r++) atomicAdd(&g_agg[i][ty+r*4][e], acc[r]);
}

// -------- kernel 9: E/G raw accumulation (split-K, 144 blocks; relu in lnprod) --------
__global__ void k_eg(const float* __restrict__ WE, const float* __restrict__ WEb,
                     const float* __restrict__ Wh, const float* __restrict__ Whb,
                     const float* __restrict__ Wqc, const float* __restrict__ Wqcb){
    __shared__ float sa[32][64];
    __shared__ float sq[32][64];
    int blk = blockIdx.x;
    int i  = blk/48;
    int et = (blk/4)%12;
    int kc = blk%4;
    int tx = threadIdx.x%64, ty = threadIdx.x/64;
    int e = et*64 + tx;
    float aE[8], aG[8];
    float bE = (kc==0)? WEb[i*Dd+e] : 0.f;
    float bG = (kc==0)? (Whb[i*Dd+e]+Wqcb[i*Dd+e]) : 0.f;
    #pragma unroll
    for(int r=0;r<8;r++){ aE[r]=bE; aG[r]=bG; }
    for(int dc=kc*192; dc<kc*192+192; dc+=64){
        __syncthreads();
        for(int q=threadIdx.x;q<32*64;q+=256){
            int bb=q/64, dd=q%64;
            sa[bb][dd]=g_agg[i][bb][dc+dd];
            sq[bb][dd]=g_Q0[i][bb][dc+dd];
        }
        __syncthreads();
        for(int d=0; d<64; d++){
            size_t off = ((size_t)i*Dd + dc+d)*Dd + e;
            float we=WE[off], wh=Wh[off], wq=Wqc[off];
            #pragma unroll
            for(int r=0;r<8;r++){
                int bb=ty+r*4;
                aE[r] += sa[bb][d]*we;
                aG[r] += sa[bb][d]*wh + sq[bb][d]*wq;
            }
        }
    }
    #pragma unroll
    for(int r=0;r<8;r++){
        int bb=ty+r*4;
        atomicAdd(&g_E[i][bb][e], aE[r]);
        atomicAdd(&g_G[i][bb][e], aG[r]);
    }
}

__device__ __forceinline__ float block_sum256(float v, float* sred){
    v = warp_sum(v);
    int wid=threadIdx.x>>5, lane=threadIdx.x&31;
    if(!lane) sred[wid]=v;
    __syncthreads();
    float t = (threadIdx.x<8)? sred[threadIdx.x] : 0.f;
    if(threadIdx.x<32){
        #pragma unroll
        for(int o=16;o>0;o>>=1) t += __shfl_xor_sync(0xffffffffu,t,o);
        if(threadIdx.x==0) sred[0]=t;
    }
    __syncthreads();
    float r = sred[0];
    __syncthreads();
    return r;
}

// -------- kernel 10: C = LN(relu(E))*LN(relu(G)) --------
__global__ void k_lnprod(const float* __restrict__ lnEg, const float* __restrict__ lnEb,
                         const float* __restrict__ lnGg, const float* __restrict__ lnGb){
    __shared__ float sred[8];
    int i = blockIdx.x/Bb, b = blockIdx.x%Bb;
    float se=0.f, se2=0.f, sg=0.f, sg2=0.f;
    for(int d=threadIdx.x; d<Dd; d+=256){
        float ev=fmaxf(g_E[i][b][d],0.f), gv=fmaxf(g_G[i][b][d],0.f);
        se+=ev; se2+=ev*ev; sg+=gv; sg2+=gv*gv;
    }
    se  = block_sum256(se , sred);
    se2 = block_sum256(se2, sred);
    sg  = block_sum256(sg , sred);
    sg2 = block_sum256(sg2, sred);
    float mE = se/(float)Dd,  vE = se2/(float)Dd - mE*mE;
    float mG = sg/(float)Dd,  vG = sg2/(float)Dd - mG*mG;
    float rE = rsqrtf(vE + LNEPS), rG = rsqrtf(vG + LNEPS);
    for(int d=threadIdx.x; d<Dd; d+=256){
        float nE = (fmaxf(g_E[i][b][d],0.f)-mE)*rE*lnEg[i*Dd+d] + lnEb[i*Dd+d];
        float nG = (fmaxf(g_G[i][b][d],0.f)-mG)*rG*lnGg[i*Dd+d] + lnGb[i*Dd+d];
        g_C[i][b][d] = nE*nG;
    }
}

// -------- kernel 11a: init dout with bias --------
__global__ void k_outinit(const float* __restrict__ out_b, float* __restrict__ dout){
    dout[(size_t)blockIdx.x*Hh + threadIdx.x] = out_b[threadIdx.x];
}

// -------- kernel 11b: out += fused @ out_w (split-K, 192 blocks) --------
__global__ void k_out(const float* __restrict__ out_w, float* __restrict__ dout){
    __shared__ float sf[32][64];
    int blk = blockIdx.x;
    int ht = blk/12;
    int kc = blk%12;
    int tx = threadIdx.x%64, ty = threadIdx.x/64;
    int h = ht*64 + tx;
    float acc[8];
    #pragma unroll
    for(int r=0;r<8;r++) acc[r]=0.f;
    for(int cc=kc*192; cc<kc*192+192; cc+=64){
        __syncthreads();
        for(int q=threadIdx.x;q<32*64;q+=256){
            int bb=q/64, d2=q%64;
            int c=cc+d2; int ii=c/Dd; int dd=c%Dd;
            sf[bb][d2]=g_C[ii][bb][dd];
        }
        __syncthreads();
        for(int d=0; d<64; d++){
            float w = out_w[((size_t)(cc+d))*Hh + h];
            #pragma unroll
            for(int r=0;r<8;r++) acc[r]+=sf[ty+r*4][d]*w;
        }
    }
    #pragma unroll
    for(int r=0;r<8;r++) atomicAdd(&dout[(size_t)(ty+r*4)*Hh + h], acc[r]);
}

// -------- kernel 12: kl scalar --------
__global__ void k_klw(float* __restrict__ dout, int write_kl){
    if(write_kl) dout[Bb*Hh] = -0.5f*(float)(Mm-1)*g_kl;
}

extern "C" void kernel_launch(void* const* d_in, const int* in_sizes, int n_in,
                              void* d_out, int out_size) {
    const float* feats = (const float*)d_in[0];
    const float* Wq    = (const float*)d_in[1];
    const float* bq    = (const float*)d_in[2];
    const float* Wk    = (const float*)d_in[3];
    const float* bk    = (const float*)d_in[4];
    const float* Wv    = (const float*)d_in[5];
    const float* bv    = (const float*)d_in[6];
    const float* pgq_w = (const float*)d_in[7];
    const float* pgq_b = (const float*)d_in[8];
    const float* pgk_w = (const float*)d_in[9];
    const float* pgk_b = (const float*)d_in[10];
    const float* mu_w  = (const float*)d_in[11];
    const float* mu_b  = (const float*)d_in[12];
    const float* lv_w  = (const float*)d_in[13];
    const float* lv_b  = (const float*)d_in[14];
    const float* dyn   = (const float*)d_in[15];
    const float* WE_w  = (const float*)d_in[16];
    const float* WE_b  = (const float*)d_in[17];
    const float* Wh_w  = (const float*)d_in[18];
    const float* Wh_b  = (const float*)d_in[19];
    const float* Wqc_w = (const float*)d_in[20];
    const float* Wqc_b = (const float*)d_in[21];
    const float* lnE_g = (const float*)d_in[22];
    const float* lnE_b = (const float*)d_in[23];
    const float* lnG_g = (const float*)d_in[24];
    const float* lnG_b = (const float*)d_in[25];
    const float* out_w = (const float*)d_in[26];
    const float* out_b = (const float*)d_in[27];
    const float* eps   = (const float*)d_in[28];
    float* dout = (float*)d_out;

    k_zero<<<256,256>>>();
    k_comp<<<576,256>>>(Wq, Wk, mu_w, lv_w, pgq_w, pgk_w);
    k_consts<<<1,576>>>(bq, bk, mu_w, mu_b, lv_w, lv_b, pgq_w, pgq_b, pgk_w, pgk_b);
    k_q0<<<144,256>>>(feats, Wq, bq);
    k_qkvec<<<144,256>>>(Wk);
    k_qbk<<<NPAIR,256>>>(bk);
    k_rowstats<<<384,256>>>(feats);
    k_attn1<<<Mm*Bb,256>>>(feats, eps, dyn);
    k_attn2<<<Mm*Bb*3,256>>>(feats);
    k_agg<<<144,256>>>(Wv, bv);
    k_eg<<<144,256>>>(WE_w, WE_b, Wh_w, Wh_b, Wqc_w, Wqc_b);
    k_lnprod<<<Mm*Bb,256>>>(lnE_g, lnE_b, lnG_g, lnG_b);
    k_outinit<<<Bb,Hh>>>(out_b, dout);
    k_out<<<192,256>>>(out_w, dout);
    k_klw<<<1,1>>>(dout, (out_size > Bb*Hh) ? 1 : 0);
}

// round 4
// speedup vs baseline: 8.3493x; 2.5491x over previous
#include <cuda_runtime.h>
#include <math.h>

#define Mm 3
#define Bb 32
#define Ss 256
#define Dd 768
#define D4 192
#define Hh 1024
#define NPAIR 6
#define LNEPS 1e-5f
#define SCALE 0.036084391824351615f

// ---------------- scratch (__device__ globals) ------------
__device__ __align__(16) float g_wmu[Mm][Dd], g_wlv[Mm][Dd], g_wpq[Mm][Dd];
__device__ float g_cmu[Mm], g_clv[Mm], g_cpq[Mm];
__device__ __align__(16) float g_wpk[Mm][Mm][Dd];
__device__ float g_cpk[Mm][Mm];
__device__ __align__(16) float g_Q0[Mm][Bb][Dd];          // atomic accum
__device__ __align__(16) float g_qkvec[Mm][Mm][Bb][Dd];   // atomic accum
__device__ float g_qbk[Mm][Mm][Bb];
__device__ float g_mu[Mm][Bb][Ss], g_lv[Mm][Bb][Ss], g_pqb[Mm][Bb][Ss];
__device__ float g_kd[Mm][Mm][Bb][Ss];
__device__ float g_dotA[Mm][Mm][Bb][Ss];                  // raw q.k dots (+qbk)
__device__ float g_W[Mm][Mm][Bb][Ss];                     // softmax weights
__device__ __align__(16) float g_wf[Mm][Mm][Bb][Dd];
__device__ __align__(16) float g_agg[Mm][Bb][Dd];         // atomic accum
__device__ __align__(16) float g_E[Mm][Bb][Dd], g_G[Mm][Bb][Dd]; // atomic accum (pre-relu)
__device__ __align__(16) float g_C[Mm][Bb][Dd];
__device__ float g_kl;

__device__ __forceinline__ float warp_sum(float v){
    #pragma unroll
    for(int o=16;o>0;o>>=1) v += __shfl_down_sync(0xffffffffu, v, o);
    return v;
}
__device__ __forceinline__ float sigmoidf(float x){ return 1.f/(1.f+expf(-x)); }
__device__ __forceinline__ float dot4(float4 a, float4 b){
    return a.x*b.x + a.y*b.y + a.z*b.z + a.w*b.w;
}

// -------- kernel 0: zero accumulators --------
__global__ void k_zero(){
    int tid = blockIdx.x*blockDim.x + threadIdx.x;
    int stride = gridDim.x*blockDim.x;
    float* p;
    p = &g_Q0[0][0][0];      for(int i=tid;i<Mm*Bb*Dd;i+=stride) p[i]=0.f;
    p = &g_qkvec[0][0][0][0];for(int i=tid;i<Mm*Mm*Bb*Dd;i+=stride) p[i]=0.f;
    p = &g_agg[0][0][0];     for(int i=tid;i<Mm*Bb*Dd;i+=stride) p[i]=0.f;
    p = &g_E[0][0][0];       for(int i=tid;i<Mm*Bb*Dd;i+=stride) p[i]=0.f;
    p = &g_G[0][0][0];       for(int i=tid;i<Mm*Bb*Dd;i+=stride) p[i]=0.f;
    if(tid==0) g_kl=0.f;
}

// -------- kernel 1: composite weight vectors --------
__global__ void k_comp(const float* __restrict__ Wq, const float* __restrict__ Wk,
                       const float* __restrict__ mu_w, const float* __restrict__ lv_w,
                       const float* __restrict__ pgq_w, const float* __restrict__ pgk_w){
    int wid = (blockIdx.x*blockDim.x + threadIdx.x)>>5;
    int lane = threadIdx.x & 31;
    if (wid < Mm*Dd){
        int m = wid/Dd, d = wid%Dd;
        const float4* row = (const float4*)(Wq + ((size_t)m*Dd + d)*Dd);
        const float4* v0 = (const float4*)(mu_w + m*Dd);
        const float4* v1 = (const float4*)(lv_w + m*Dd);
        const float4* v2 = (const float4*)(pgq_w + m*Dd);
        float a=0.f,b=0.f,c=0.f;
        for(int e=lane;e<D4;e+=32){
            float4 w = row[e];
            a += dot4(w,v0[e]); b += dot4(w,v1[e]); c += dot4(w,v2[e]);
        }
        a=warp_sum(a); b=warp_sum(b); c=warp_sum(c);
        if(!lane){ g_wmu[m][d]=a; g_wlv[m][d]=b; g_wpq[m][d]=c; }
    } else {
        int w2 = wid - Mm*Dd;
        if (w2 >= Mm*Dd) return;
        int j = w2/Dd, d = w2%Dd;
        const float4* row = (const float4*)(Wk + ((size_t)j*Dd + d)*Dd);
        const float4* v0 = (const float4*)(pgk_w + 0*Dd);
        const float4* v1 = (const float4*)(pgk_w + 1*Dd);
        const float4* v2 = (const float4*)(pgk_w + 2*Dd);
        float a=0.f,b=0.f,c=0.f;
        for(int e=lane;e<D4;e+=32){
            float4 w = row[e];
            a += dot4(w,v0[e]); b += dot4(w,v1[e]); c += dot4(w,v2[e]);
        }
        a=warp_sum(a); b=warp_sum(b); c=warp_sum(c);
        if(!lane){ g_wpk[0][j][d]=a; g_wpk[1][j][d]=b; g_wpk[2][j][d]=c; }
    }
}

// -------- kernel 2: scalar constants --------
__global__ void k_consts(const float* __restrict__ bq, const float* __restrict__ bk,
                         const float* __restrict__ mu_w, const float* __restrict__ mu_b,
                         const float* __restrict__ lv_w, const float* __restrict__ lv_b,
                         const float* __restrict__ pgq_w, const float* __restrict__ pgq_b,
                         const float* __restrict__ pgk_w, const float* __restrict__ pgk_b){
    int t = threadIdx.x>>5, lane = threadIdx.x&31;
    if (t < 9){
        int m = t/3, which = t%3;
        const float* wv = (which==0)? mu_w : (which==1)? lv_w : pgq_w;
        float a=0.f;
        for(int e=lane;e<Dd;e+=32) a += bq[m*Dd+e]*wv[m*Dd+e];
        a=warp_sum(a);
        if(!lane){
            if(which==0) g_cmu[m]=a+mu_b[m];
            else if(which==1) g_clv[m]=a+lv_b[m];
            else g_cpq[m]=a+pgq_b[m];
        }
    } else if (t < 18){
        int q=t-9; int i=q/3, j=q%3;
        float a=0.f;
        for(int e=lane;e<Dd;e+=32) a += bk[j*Dd+e]*pgk_w[i*Dd+e];
        a=warp_sum(a);
        if(!lane) g_cpk[i][j]=a+pgk_b[i];
    }
}

// -------- kernel 3: Q0 += feats[:,:,0,:] @ Wq (split-K 6, W staged in smem) --------
__global__ void k_q0(const float* __restrict__ feats, const float* __restrict__ Wq,
                     const float* __restrict__ bq){
    __shared__ float sh[32][64];
    __shared__ float shw[64][64];
    int blk = blockIdx.x;
    int i = blk/72; int rem = blk%72; int et = rem/6; int kc = rem%6;
    int tx = threadIdx.x%64, ty = threadIdx.x/64;
    int e = et*64 + tx;
    float acc[8];
    float binit = (kc==0)? bq[i*Dd+e] : 0.f;
    #pragma unroll
    for(int r=0;r<8;r++) acc[r]=binit;
    for(int dc=kc*128; dc<kc*128+128; dc+=64){
        __syncthreads();
        for(int q=threadIdx.x;q<512;q+=256){
            int bb=q/16, dd4=q%16;
            ((float4*)sh[bb])[dd4] =
                ((const float4*)(feats + (((size_t)i*Bb+bb)*Ss)*Dd + dc))[dd4];
        }
        for(int q=threadIdx.x;q<1024;q+=256){
            int rr=q/16, cc=q%16;
            ((float4*)shw[rr])[cc] =
                ((const float4*)(Wq + ((size_t)i*Dd + dc+rr)*Dd + et*64))[cc];
        }
        __syncthreads();
        #pragma unroll 8
        for(int d=0; d<64; d++){
            float w = shw[d][tx];
            #pragma unroll
            for(int r=0;r<8;r++) acc[r] += sh[ty+r*4][d]*w;
        }
    }
    #pragma unroll
    for(int r=0;r<8;r++) atomicAdd(&g_Q0[i][ty+r*4][e], acc[r]);
}

// -------- kernel 4: qkvec += Wk[j] @ Q0 (split-K 6, transposed W in smem) --------
__global__ void k_qkvec(const float* __restrict__ Wk){
    __shared__ float shq[64][64];
    __shared__ float shw[64][65];   // transposed: shw[ee][rr]
    int blk = blockIdx.x;
    int j = blk/72; int rem = blk%72; int dt = rem/6; int kc = rem%6;
    int i0 = (j==0)?1:0, i1 = (j==2)?1:2;
    int tx = threadIdx.x%64, ty = threadIdx.x/64;
    int d = dt*64 + tx;
    float acc[16];
    #pragma unroll
    for(int r=0;r<16;r++) acc[r]=0.f;
    for(int ec=kc*128; ec<kc*128+128; ec+=64){
        __syncthreads();
        for(int q=threadIdx.x;q<1024;q+=256){
            int rr=q/16, cc=q%16;
            int ii=(rr<32)?i0:i1; int bb=rr&31;
            ((float4*)shq[rr])[cc] = ((const float4*)(&g_Q0[ii][bb][ec]))[cc];
        }
        for(int q=threadIdx.x;q<1024;q+=256){
            int rr=q/16, cc=q%16;
            float4 w4 = ((const float4*)(Wk + ((size_t)j*Dd + dt*64 + rr)*Dd + ec))[cc];
            shw[cc*4+0][rr]=w4.x; shw[cc*4+1][rr]=w4.y;
            shw[cc*4+2][rr]=w4.z; shw[cc*4+3][rr]=w4.w;
        }
        __syncthreads();
        #pragma unroll 4
        for(int ee=0; ee<64; ee++){
            float w = shw[ee][tx];
            #pragma unroll
            for(int r=0;r<16;r++) acc[r] += shq[ty+r*4][ee]*w;
        }
    }
    #pragma unroll
    for(int r=0;r<16;r++){
        int vv = ty + r*4; int ii=(vv<32)?i0:i1; int bb=vv&31;
        atomicAdd(&g_qkvec[ii][j][bb][d], acc[r]);
    }
}

// -------- kernel 5: qbk[i,j,b] = bk[j] . Q0[i,b] --------
__global__ void k_qbk(const float* __restrict__ bk){
    const int pi[NPAIR]={0,0,1,1,2,2}, pj[NPAIR]={1,2,0,2,0,1};
    int p = blockIdx.x; int i=pi[p], j=pj[p];
    int wid=threadIdx.x>>5, lane=threadIdx.x&31;
    for(int b=wid;b<Bb;b+=8){
        float a=0.f;
        for(int e=lane;e<Dd;e+=32) a += bk[j*Dd+e]*g_Q0[i][b][e];
        a=warp_sum(a);
        if(!lane) g_qbk[i][j][b]=a;
    }
}

// -------- kernel 6: FUSED row stats + attention dots + kl (single feats pass) --------
__global__ void k_rowstats(const float* __restrict__ feats){
    __shared__ float4 sw4[7][D4];
    __shared__ float skl[8];
    int blk = blockIdx.x;
    int m  = blk/(Bb*4);
    int b  = (blk/4)%Bb;
    int sc = blk%4;
    int i0=(m==0)?1:0, i1=(m==2)?1:2;
    for(int d=threadIdx.x; d<D4; d+=256){
        sw4[0][d]=((const float4*)g_wmu[m])[d];
        sw4[1][d]=((const float4*)g_wlv[m])[d];
        sw4[2][d]=((const float4*)g_wpq[m])[d];
        sw4[3][d]=((const float4*)g_wpk[i0][m])[d];
        sw4[4][d]=((const float4*)g_wpk[i1][m])[d];
        sw4[5][d]=((const float4*)g_qkvec[i0][m][b])[d];
        sw4[6][d]=((const float4*)g_qkvec[i1][m][b])[d];
    }
    __syncthreads();
    int wid=threadIdx.x>>5, lane=threadIdx.x&31;
    float qb0 = g_qbk[i0][m][b], qb1 = g_qbk[i1][m][b];
    float klacc=0.f;
    const float* base = feats + ((size_t)m*Bb+b)*Ss*Dd;
    int s0 = sc*64 + wid*8;
    for(int t=0;t<8;t+=2){
        int s = s0 + t;
        const float4* f0 = (const float4*)(base + (size_t)s*Dd);
        const float4* f1 = f0 + D4;
        float a0=0,a1=0,a2=0,a3=0,a4=0,a5=0,a6=0;
        float c0=0,c1=0,c2=0,c3=0,c4=0,c5=0,c6=0;
        for(int d=lane; d<D4; d+=32){
            float4 x0=f0[d], x1=f1[d];
            a0+=dot4(x0,sw4[0][d]); c0+=dot4(x1,sw4[0][d]);
            a1+=dot4(x0,sw4[1][d]); c1+=dot4(x1,sw4[1][d]);
            a2+=dot4(x0,sw4[2][d]); c2+=dot4(x1,sw4[2][d]);
            a3+=dot4(x0,sw4[3][d]); c3+=dot4(x1,sw4[3][d]);
            a4+=dot4(x0,sw4[4][d]); c4+=dot4(x1,sw4[4][d]);
            a5+=dot4(x0,sw4[5][d]); c5+=dot4(x1,sw4[5][d]);
            a6+=dot4(x0,sw4[6][d]); c6+=dot4(x1,sw4[6][d]);
        }
        a0=warp_sum(a0); a1=warp_sum(a1); a2=warp_sum(a2); a3=warp_sum(a3);
        a4=warp_sum(a4); a5=warp_sum(a5); a6=warp_sum(a6);
        c0=warp_sum(c0); c1=warp_sum(c1); c2=warp_sum(c2); c3=warp_sum(c3);
        c4=warp_sum(c4); c5=warp_sum(c5); c6=warp_sum(c6);
        if(!lane){
            float mu=a0+g_cmu[m], lv=a1+g_clv[m];
            g_mu[m][b][s]=mu; g_lv[m][b][s]=lv;
            g_pqb[m][b][s]=a2+g_cpq[m];
            g_kd[i0][m][b][s]=a3+g_cpk[i0][m];
            g_kd[i1][m][b][s]=a4+g_cpk[i1][m];
            g_dotA[i0][m][b][s]=a5+qb0;
            g_dotA[i1][m][b][s]=a6+qb1;
            klacc += 1.f + lv - mu*mu - expf(lv);
            float mu2=c0+g_cmu[m], lv2=c1+g_clv[m];
            g_mu[m][b][s+1]=mu2; g_lv[m][b][s+1]=lv2;
            g_pqb[m][b][s+1]=c2+g_cpq[m];
            g_kd[i0][m][b][s+1]=c3+g_cpk[i0][m];
            g_kd[i1][m][b][s+1]=c4+g_cpk[i1][m];
            g_dotA[i0][m][b][s+1]=c5+qb0;
            g_dotA[i1][m][b][s+1]=c6+qb1;
            klacc += 1.f + lv2 - mu2*mu2 - expf(lv2);
        }
    }
    if(!lane) skl[wid]=klacc;
    __syncthreads();
    if(threadIdx.x==0){
        float t=0.f;
        #pragma unroll
        for(int w=0;w<8;w++) t+=skl[w];
        atomicAdd(&g_kl, t);
    }
}

// -------- kernel 7: gates + softmax (both pairs per (j,b)) --------
__global__ void k_gates(const float* __restrict__ eps, const float* __restrict__ dyn){
    __shared__ float sred[8];
    __shared__ float spq0, spq1, sscal;
    int j = blockIdx.x/Bb, b = blockIdx.x%Bb;
    int i0=(j==0)?1:0, i1=(j==2)?1:2;
    int cnt0 = (j<i0)? j : j-1;
    int cnt1 = (j<i1)? j : j-1;
    int k = threadIdx.x;
    int wid=k>>5, lane=k&31;
    float dynv = dyn[0];
    float mu0=g_mu[i0][b][k], lv0=g_lv[i0][b][k];
    float e0 = eps[(((size_t)i0*(Mm-1)+cnt0)*Bb + b)*Ss + k];
    float gk0 = sigmoidf(mu0 + dynv*expf(0.5f*lv0)*e0);
    float pk0 = sigmoidf(g_kd[i0][j][b][k]) * gk0;
    float mu1=g_mu[i1][b][k], lv1=g_lv[i1][b][k];
    float e1 = eps[(((size_t)i1*(Mm-1)+cnt1)*Bb + b)*Ss + k];
    float gk1 = sigmoidf(mu1 + dynv*expf(0.5f*lv1)*e1);
    float pk1 = sigmoidf(g_kd[i1][j][b][k]) * gk1;
    if(k==0){
        spq0 = sigmoidf(g_pqb[i0][b][0]) * gk0;
        spq1 = sigmoidf(g_pqb[i1][b][0]) * gk1;
    }
    __syncthreads();
    float l0 = g_dotA[i0][j][b][k]*SCALE*spq0*pk0;
    float l1 = g_dotA[i1][j][b][k]*SCALE*spq1*pk1;
    {
        float mx=l0;
        #pragma unroll
        for(int o=16;o>0;o>>=1) mx=fmaxf(mx,__shfl_xor_sync(0xffffffffu,mx,o));
        if(!lane) sred[wid]=mx;
        __syncthreads();
        if(threadIdx.x==0){ float t=sred[0];
            #pragma unroll
            for(int w=1;w<8;w++) t=fmaxf(t,sred[w]); sscal=t; }
        __syncthreads();
        float ex=expf(l0-sscal);
        float sm=ex;
        #pragma unroll
        for(int o=16;o>0;o>>=1) sm+=__shfl_xor_sync(0xffffffffu,sm,o);
        if(!lane) sred[wid]=sm;
        __syncthreads();
        if(threadIdx.x==0){ float t=0.f;
            #pragma unroll
            for(int w=0;w<8;w++) t+=sred[w]; sscal=t; }
        __syncthreads();
        g_W[i0][j][b][k]=ex/sscal;
        __syncthreads();
    }
    {
        float mx=l1;
        #pragma unroll
        for(int o=16;o>0;o>>=1) mx=fmaxf(mx,__shfl_xor_sync(0xffffffffu,mx,o));
        if(!lane) sred[wid]=mx;
        __syncthreads();
        if(threadIdx.x==0){ float t=sred[0];
            #pragma unroll
            for(int w=1;w<8;w++) t=fmaxf(t,sred[w]); sscal=t; }
        __syncthreads();
        float ex=expf(l1-sscal);
        float sm=ex;
        #pragma unroll
        for(int o=16;o>0;o>>=1) sm+=__shfl_xor_sync(0xffffffffu,sm,o);
        if(!lane) sred[wid]=sm;
        __syncthreads();
        if(threadIdx.x==0){ float t=0.f;
            #pragma unroll
            for(int w=0;w<8;w++) t+=sred[w]; sscal=t; }
        __syncthreads();
        g_W[i1][j][b][k]=ex/sscal;
    }
}

// -------- kernel 8: weighted feats sums for BOTH i; d-split (288 blocks) --------
__global__ void k_attn2(const float* __restrict__ feats){
    __shared__ float w0[Ss], w1[Ss];
    int blk = blockIdx.x;
    int j  = blk/(Bb*3);
    int b  = (blk/3)%Bb;
    int dc = blk%3;
    int i0=(j==0)?1:0, i1=(j==2)?1:2;
    if(threadIdx.x < Ss){
        w0[threadIdx.x]=g_W[i0][j][b][threadIdx.x];
        w1[threadIdx.x]=g_W[i1][j][b][threadIdx.x];
    }
    __syncthreads();
    int d = dc*256 + threadIdx.x;
    const float* ftile = feats + (((size_t)j*Bb+b)*Ss)*Dd;
    float acc0=0.f, acc1=0.f;
    #pragma unroll 8
    for(int k=0;k<Ss;k++){
        float f = ftile[(size_t)k*Dd + d];
        acc0 += w0[k]*f; acc1 += w1[k]*f;
    }
    g_wf[i0][j][b][d]=acc0;
    g_wf[i1][j][b][d]=acc1;
}

// -------- kernel 9: agg[i] += wf[i,j] @ Wv[j] (j folded into split-K; 288 blocks) --------
__global__ void k_agg(const float* __restrict__ Wv, const float* __restrict__ bv){
    __shared__ float sh[32][64];
    __shared__ float shw[64][64];
    int blk = blockIdx.x;
    int i  = blk/96;
    int rem = blk%96;
    int et = rem/8;
    int q8 = rem%8;
    int jj = q8>>2, kc = q8&3;
    int j0=(i==0)?1:0, j1=(i==2)?1:2;
    int j = jj? j1 : j0;
    int tx = threadIdx.x%64, ty = threadIdx.x/64;
    int e = et*64 + tx;
    float acc[8];
    float binit = (kc==0)? bv[j*Dd+e] : 0.f;
    #pragma unroll
    for(int r=0;r<8;r++) acc[r]=binit;
    for(int dc=kc*192; dc<kc*192+192; dc+=64){
        __syncthreads();
        for(int q=threadIdx.x;q<512;q+=256){
            int bb=q/16, dd4=q%16;
            ((float4*)sh[bb])[dd4] = ((const float4*)(&g_wf[i][j][bb][dc]))[dd4];
        }
        for(int q=threadIdx.x;q<1024;q+=256){
            int rr=q/16, cc=q%16;
            ((float4*)shw[rr])[cc] =
                ((const float4*)(Wv + ((size_t)j*Dd + dc+rr)*Dd + et*64))[cc];
        }
        __syncthreads();
        #pragma unroll 8
        for(int d=0; d<64; d++){
            float w = shw[d][tx];
            #pragma unroll
            for(int r=0;r<8;r++) acc[r] += sh[ty+r*4][d]*w;
        }
    }
    #pragma unroll
    for(int r=0;r<8;r++) atomicAdd(&g_agg[i][ty+r*4][e], acc[r]);
}

// -------- kernel 10: E/G accumulation (3 segments x split-K 4; 432 blocks) --------
__global__ void k_eg(const float* __restrict__ WE, const float* __restrict__ WEb,
                     const float* __restrict__ Wh, const float* __restrict__ Whb,
                     const float* __restrict__ Wqc, const float* __restrict__ Wqcb){
    __shared__ float sh[32][64];
    __shared__ float shw[64][64];
    int blk = blockIdx.x;
    int i  = blk/144;
    int rem = blk%144;
    int et = rem/12;
    int s12 = rem%12;
    int seg = s12>>2, kc = s12&3;
    int tx = threadIdx.x%64, ty = threadIdx.x/64;
    int e = et*64 + tx;
    const float* W = (seg==0)? WE : (seg==1)? Wh : Wqc;
    const float* src = (seg==2)? &g_Q0[i][0][0] : &g_agg[i][0][0];
    float* dst = (seg==0)? &g_E[i][0][0] : &g_G[i][0][0];
    float acc[8];
    float binit = 0.f;
    if(kc==0){
        if(seg==0) binit = WEb[i*Dd+e];
        else if(seg==1) binit = Whb[i*Dd+e]+Wqcb[i*Dd+e];
    }
    #pragma unroll
    for(int r=0;r<8;r++) acc[r]=binit;
    for(int dc=kc*192; dc<kc*192+192; dc+=64){
        __syncthreads();
        for(int q=threadIdx.x;q<512;q+=256){
            int bb=q/16, dd4=q%16;
            ((float4*)sh[bb])[dd4] = ((const float4*)(src + (size_t)bb*Dd + dc))[dd4];
        }
        for(int q=threadIdx.x;q<1024;q+=256){
            int rr=q/16, cc=q%16;
            ((float4*)shw[rr])[cc] =
                ((const float4*)(W + ((size_t)i*Dd + dc+rr)*Dd + et*64))[cc];
        }
        __syncthreads();
        #pragma unroll 8
        for(int d=0; d<64; d++){
            float w = shw[d][tx];
            #pragma unroll
            for(int r=0;r<8;r++) acc[r] += sh[ty+r*4][d]*w;
        }
    }
    #pragma unroll
    for(int r=0;r<8;r++) atomicAdd(dst + (size_t)(ty+r*4)*Dd + e, acc[r]);
}

__device__ __forceinline__ float block_sum256(float v, float* sred){
    v = warp_sum(v);
    int wid=threadIdx.x>>5, lane=threadIdx.x&31;
    if(!lane) sred[wid]=v;
    __syncthreads();
    float t = (threadIdx.x<8)? sred[threadIdx.x] : 0.f;
    if(threadIdx.x<32){
        #pragma unroll
        for(int o=16;o>0;o>>=1) t += __shfl_xor_sync(0xffffffffu,t,o);
        if(threadIdx.x==0) sred[0]=t;
    }
    __syncthreads();
    float r = sred[0];
    __syncthreads();
    return r;
}

// -------- kernel 11: C = LN(relu(E))*LN(relu(G)) --------
__global__ void k_lnprod(const float* __restrict__ lnEg, const float* __restrict__ lnEb,
                         const float* __restrict__ lnGg, const float* __restrict__ lnGb){
    __shared__ float sred[8];
    int i = blockIdx.x/Bb, b = blockIdx.x%Bb;
    float se=0.f, se2=0.f, sg=0.f, sg2=0.f;
    for(int d=threadIdx.x; d<Dd; d+=256){
        float ev=fmaxf(g_E[i][b][d],0.f), gv=fmaxf(g_G[i][b][d],0.f);
        se+=ev; se2+=ev*ev; sg+=gv; sg2+=gv*gv;
    }
    se  = block_sum256(se , sred);
    se2 = block_sum256(se2, sred);
    sg  = block_sum256(sg , sred);
    sg2 = block_sum256(sg2, sred);
    float mE = se/(float)Dd,  vE = se2/(float)Dd - mE*mE;
    float mG = sg/(float)Dd,  vG = sg2/(float)Dd - mG*mG;
    float rE = rsqrtf(vE + LNEPS), rG = rsqrtf(vG + LNEPS);
    for(int d=threadIdx.x; d<Dd; d+=256){
        float nE = (fmaxf(g_E[i][b][d],0.f)-mE)*rE*lnEg[i*Dd+d] + lnEb[i*Dd+d];
        float nG = (fmaxf(g_G[i][b][d],0.f)-mG)*rG*lnGg[i*Dd+d] + lnGb[i*Dd+d];
        g_C[i][b][d] = nE*nG;
    }
}

// -------- kernel 12a: init dout with bias --------
__global__ void k_outinit(const float* __restrict__ out_b, float* __restrict__ dout){
    dout[(size_t)blockIdx.x*Hh + threadIdx.x] = out_b[threadIdx.x];
}

// -------- kernel 12b: out += fused @ out_w (split-K 12, W staged) --------
__global__ void k_out(const float* __restrict__ out_w, float* __restrict__ dout){
    __shared__ float sf[32][64];
    __shared__ float shw[64][64];
    int blk = blockIdx.x;
    int ht = blk/12;
    int kc = blk%12;
    int ii = kc/4;
    int dbase = (kc%4)*192;
    int tx = threadIdx.x%64, ty = threadIdx.x/64;
    int h = ht*64 + tx;
    float acc[8];
    #pragma unroll
    for(int r=0;r<8;r++) acc[r]=0.f;
    for(int dcl=0; dcl<192; dcl+=64){
        __syncthreads();
        for(int q=threadIdx.x;q<512;q+=256){
            int bb=q/16, dd4=q%16;
            ((float4*)sf[bb])[dd4] = ((const float4*)(&g_C[ii][bb][dbase+dcl]))[dd4];
        }
        for(int q=threadIdx.x;q<1024;q+=256){
            int rr=q/16, cc=q%16;
            ((float4*)shw[rr])[cc] =
                ((const float4*)(out_w + ((size_t)(kc*192+dcl+rr))*Hh + ht*64))[cc];
        }
        __syncthreads();
        #pragma unroll 8
        for(int d=0; d<64; d++){
            float w = shw[d][tx];
            #pragma unroll
            for(int r=0;r<8;r++) acc[r]+=sf[ty+r*4][d]*w;
        }
    }
    #pragma unroll
    for(int r=0;r<8;r++) atomicAdd(&dout[(size_t)(ty+r*4)*Hh + h], acc[r]);
}

// -------- kernel 13: kl scalar --------
__global__ void k_klw(float* __restrict__ dout, int write_kl){
    if(write_kl) dout[Bb*Hh] = -0.5f*(float)(Mm-1)*g_kl;
}

extern "C" void kernel_launch(void* const* d_in, const int* in_sizes, int n_in,
                              void* d_out, int out_size) {
    const float* feats = (const float*)d_in[0];
    const float* Wq    = (const float*)d_in[1];
    const float* bq    = (const float*)d_in[2];
    const float* Wk    = (const float*)d_in[3];
    const float* bk    = (const float*)d_in[4];
    const float* Wv    = (const float*)d_in[5];
    const float* bv    = (const float*)d_in[6];
    const float* pgq_w = (const float*)d_in[7];
    const float* pgq_b = (const float*)d_in[8];
    const float* pgk_w = (const float*)d_in[9];
    const float* pgk_b = (const float*)d_in[10];
    const float* mu_w  = (const float*)d_in[11];
    const float* mu_b  = (const float*)d_in[12];
    const float* lv_w  = (const float*)d_in[13];
    const float* lv_b  = (const float*)d_in[14];
    const float* dyn   = (const float*)d_in[15];
    const float* WE_w  = (const float*)d_in[16];
    const float* WE_b  = (const float*)d_in[17];
    const float* Wh_w  = (const float*)d_in[18];
    const float* Wh_b  = (const float*)d_in[19];
    const float* Wqc_w = (const float*)d_in[20];
    const float* Wqc_b = (const float*)d_in[21];
    const float* lnE_g = (const float*)d_in[22];
    const float* lnE_b = (const float*)d_in[23];
    const float* lnG_g = (const float*)d_in[24];
    const float* lnG_b = (const float*)d_in[25];
    const float* out_w = (const float*)d_in[26];
    const float* out_b = (const float*)d_in[27];
    const float* eps   = (const float*)d_in[28];
    float* dout = (float*)d_out;

    k_zero<<<256,256>>>();
    k_comp<<<576,256>>>(Wq, Wk, mu_w, lv_w, pgq_w, pgk_w);
    k_consts<<<1,576>>>(bq, bk, mu_w, mu_b, lv_w, lv_b, pgq_w, pgq_b, pgk_w, pgk_b);
    k_q0<<<216,256>>>(feats, Wq, bq);
    k_qkvec<<<216,256>>>(Wk);
    k_qbk<<<NPAIR,256>>>(bk);
    k_rowstats<<<384,256>>>(feats);
    k_gates<<<Mm*Bb,256>>>(eps, dyn);
    k_attn2<<<Mm*Bb*3,256>>>(feats);
    k_agg<<<288,256>>>(Wv, bv);
    k_eg<<<432,256>>>(WE_w, WE_b, Wh_w, Wh_b, Wqc_w, Wqc_b);
    k_lnprod<<<Mm*Bb,256>>>(lnE_g, lnE_b, lnG_g, lnG_b);
    k_outinit<<<Bb,Hh>>>(out_b, dout);
    k_out<<<192,256>>>(out_w, dout);
    k_klw<<<1,1>>>(dout, (out_size > Bb*Hh) ? 1 : 0);
}

// round 5
// speedup vs baseline: 9.8094x; 1.1749x over previous
#include <cuda_runtime.h>
#include <math.h>

#define Mm 3
#define Bb 32
#define Ss 256
#define Dd 768
#define D4 192
#define Hh 1024
#define NPAIR 6
#define LNEPS 1e-5f
#define SCALE 0.036084391824351615f

// ---------------- scratch (__device__ globals) ------------
__device__ __align__(16) float g_wmu[Mm][Dd], g_wlv[Mm][Dd], g_wpq[Mm][Dd]; // atomic accum
__device__ float g_cmu[Mm], g_clv[Mm], g_cpq[Mm];
__device__ __align__(16) float g_wpk[Mm][Mm][Dd];                            // atomic accum
__device__ float g_cpk[Mm][Mm];
__device__ __align__(16) float g_Q0[Mm][Bb][Dd];          // atomic accum
__device__ __align__(16) float g_qkvec[Mm][Mm][Bb][Dd];   // atomic accum
__device__ float g_qbk[Mm][Mm][Bb];
__device__ float g_mu[Mm][Bb][Ss], g_lv[Mm][Bb][Ss], g_pqb[Mm][Bb][Ss];
__device__ float g_kd[Mm][Mm][Bb][Ss];
__device__ float g_dotA[Mm][Mm][Bb][Ss];
__device__ __align__(16) float g_wf[Mm][Mm][Bb][Dd];
__device__ __align__(16) float g_agg[Mm][Bb][Dd];         // atomic accum
__device__ __align__(16) float g_E[Mm][Bb][Dd], g_G[Mm][Bb][Dd]; // atomic accum
__device__ __align__(16) float g_C[Mm][Bb][Dd];
__device__ float g_kl;

__device__ __forceinline__ float warp_sum(float v){
    #pragma unroll
    for(int o=16;o>0;o>>=1) v += __shfl_down_sync(0xffffffffu, v, o);
    return v;
}
__device__ __forceinline__ float sigmoidf(float x){ return 1.f/(1.f+expf(-x)); }
__device__ __forceinline__ float dot4(float4 a, float4 b){
    return a.x*b.x + a.y*b.y + a.z*b.z + a.w*b.w;
}

// ======== kernel 1: zero accumulators + scalar constants ========
__global__ void k_init(const float* __restrict__ bq, const float* __restrict__ bk,
                       const float* __restrict__ mu_w, const float* __restrict__ mu_b,
                       const float* __restrict__ lv_w, const float* __restrict__ lv_b,
                       const float* __restrict__ pgq_w, const float* __restrict__ pgq_b,
                       const float* __restrict__ pgk_w, const float* __restrict__ pgk_b){
    if(blockIdx.x < 160){
        int tid = blockIdx.x*256 + threadIdx.x;
        const int stride = 160*256;
        float* p;
        p=&g_Q0[0][0][0];       for(int i=tid;i<Mm*Bb*Dd;i+=stride)    p[i]=0.f;
        p=&g_qkvec[0][0][0][0]; for(int i=tid;i<Mm*Mm*Bb*Dd;i+=stride) p[i]=0.f;
        p=&g_agg[0][0][0];      for(int i=tid;i<Mm*Bb*Dd;i+=stride)    p[i]=0.f;
        p=&g_E[0][0][0];        for(int i=tid;i<Mm*Bb*Dd;i+=stride)    p[i]=0.f;
        p=&g_G[0][0][0];        for(int i=tid;i<Mm*Bb*Dd;i+=stride)    p[i]=0.f;
        p=&g_wmu[0][0];         for(int i=tid;i<Mm*Dd;i+=stride)       p[i]=0.f;
        p=&g_wlv[0][0];         for(int i=tid;i<Mm*Dd;i+=stride)       p[i]=0.f;
        p=&g_wpq[0][0];         for(int i=tid;i<Mm*Dd;i+=stride)       p[i]=0.f;
        p=&g_wpk[0][0][0];      for(int i=tid;i<Mm*Mm*Dd;i+=stride)    p[i]=0.f;
        if(tid==0) g_kl=0.f;
    } else {
        int wid=threadIdx.x>>5, lane=threadIdx.x&31;
        for(int t=wid;t<18;t+=8){
            if(t<9){
                int m=t/3, which=t%3;
                const float* wv = (which==0)? mu_w : (which==1)? lv_w : pgq_w;
                float a=0.f;
                for(int e=lane;e<Dd;e+=32) a += bq[m*Dd+e]*wv[m*Dd+e];
                a=warp_sum(a);
                if(!lane){
                    if(which==0) g_cmu[m]=a+mu_b[m];
                    else if(which==1) g_clv[m]=a+lv_b[m];
                    else g_cpq[m]=a+pgq_b[m];
                }
            } else {
                int q=t-9; int i=q/3, j=q%3;
                float a=0.f;
                for(int e=lane;e<Dd;e+=32) a += bk[j*Dd+e]*pgk_w[i*Dd+e];
                a=warp_sum(a);
                if(!lane) g_cpk[i][j]=a+pgk_b[i];
            }
        }
    }
}

// ======== kernel 2: Q0 GEMM + wmu/wlv/wpq composites (Wq read once) ========
// 432 single-tile blocks: (i, e-tile, k-tile)
__global__ void k_q0(const float* __restrict__ feats, const float* __restrict__ Wq,
                     const float* __restrict__ bq,
                     const float* __restrict__ mu_w, const float* __restrict__ lv_w,
                     const float* __restrict__ pgq_w){
    __shared__ float sh[32][64];
    __shared__ float shw[64][64];
    int blk=blockIdx.x;
    int i=blk/144; int rem=blk%144; int et=rem/12; int kc=rem%12;
    int tx=threadIdx.x&63, ty=threadIdx.x>>6;
    int e=et*64+tx;
    int dbase=kc*64;
    for(int q=threadIdx.x;q<512;q+=256){
        int bb=q>>4, dd4=q&15;
        ((float4*)sh[bb])[dd4] =
            ((const float4*)(feats + (((size_t)i*Bb+bb)*Ss)*Dd + dbase))[dd4];
    }
    for(int q=threadIdx.x;q<1024;q+=256){
        int rr=q>>4, cc=q&15;
        ((float4*)shw[rr])[cc] =
            ((const float4*)(Wq + ((size_t)i*Dd + dbase+rr)*Dd + et*64))[cc];
    }
    __syncthreads();
    float acc[8];
    float binit=(kc==0)? bq[i*Dd+e] : 0.f;
    #pragma unroll
    for(int r=0;r<8;r++) acc[r]=binit;
    #pragma unroll 8
    for(int d=0;d<64;d++){
        float w=shw[d][tx];
        #pragma unroll
        for(int r=0;r<8;r++) acc[r]+=sh[ty+r*4][d]*w;
    }
    #pragma unroll
    for(int r=0;r<8;r++) atomicAdd(&g_Q0[i][ty+r*4][e], acc[r]);
    // composite dots: rows d=dbase+rr, partial over e-range of this tile
    int wid=threadIdx.x>>5, lane=threadIdx.x&31;
    int ea=et*64+lane, eb=ea+32;
    float m0=mu_w[i*Dd+ea],  m1=mu_w[i*Dd+eb];
    float l0=lv_w[i*Dd+ea],  l1=lv_w[i*Dd+eb];
    float p0=pgq_w[i*Dd+ea], p1=pgq_w[i*Dd+eb];
    for(int rr=wid*8; rr<wid*8+8; rr++){
        float w0=shw[rr][lane], w1=shw[rr][lane+32];
        float a=w0*m0+w1*m1, b=w0*l0+w1*l1, c=w0*p0+w1*p1;
        a=warp_sum(a); b=warp_sum(b); c=warp_sum(c);
        if(!lane){
            atomicAdd(&g_wmu[i][dbase+rr],a);
            atomicAdd(&g_wlv[i][dbase+rr],b);
            atomicAdd(&g_wpq[i][dbase+rr],c);
        }
    }
}

// ======== kernel 3: qkvec GEMM + wpk composites (Wk read once) + qbk ========
// 432 single-tile blocks + 6 qbk blocks
__global__ void k_qkvec(const float* __restrict__ Wk, const float* __restrict__ bk,
                        const float* __restrict__ pgk_w){
    int blk=blockIdx.x;
    if(blk>=432){
        const int pi[6]={0,0,1,1,2,2}, pj[6]={1,2,0,2,0,1};
        int p=blk-432; int i=pi[p], j=pj[p];
        int wid=threadIdx.x>>5, lane=threadIdx.x&31;
        for(int b=wid;b<Bb;b+=8){
            float a=0.f;
            for(int e=lane;e<Dd;e+=32) a += bk[j*Dd+e]*g_Q0[i][b][e];
            a=warp_sum(a);
            if(!lane) g_qbk[i][j][b]=a;
        }
        return;
    }
    __shared__ float shq[64][64];
    __shared__ float shw[64][65];   // transposed: shw[ee][rr]
    int j=blk/144; int rem=blk%144; int dt=rem/12; int kc=rem%12;
    int i0=(j==0)?1:0, i1=(j==2)?1:2;
    int tx=threadIdx.x&63, ty=threadIdx.x>>6;
    int d=dt*64+tx;
    int ebase=kc*64;
    for(int q=threadIdx.x;q<1024;q+=256){
        int rr=q>>4, cc=q&15;
        int ii=(rr<32)?i0:i1; int bb=rr&31;
        ((float4*)shq[rr])[cc] = ((const float4*)(&g_Q0[ii][bb][ebase]))[cc];
    }
    for(int q=threadIdx.x;q<1024;q+=256){
        int rr=q>>4, cc=q&15;
        float4 w4 = ((const float4*)(Wk + ((size_t)j*Dd + dt*64+rr)*Dd + ebase))[cc];
        shw[cc*4+0][rr]=w4.x; shw[cc*4+1][rr]=w4.y;
        shw[cc*4+2][rr]=w4.z; shw[cc*4+3][rr]=w4.w;
    }
    __syncthreads();
    float acc[16];
    #pragma unroll
    for(int r=0;r<16;r++) acc[r]=0.f;
    #pragma unroll 4
    for(int ee=0;ee<64;ee++){
        float w=shw[ee][tx];
        #pragma unroll
        for(int r=0;r<16;r++) acc[r]+=shq[ty+r*4][ee]*w;
    }
    #pragma unroll
    for(int r=0;r<16;r++){
        int vv=ty+r*4; int ii=(vv<32)?i0:i1; int bb=vv&31;
        atomicAdd(&g_qkvec[ii][j][bb][d], acc[r]);
    }
    // wpk composites: rows d=dt*64+rr, partial over ee range of this tile
    int wid=threadIdx.x>>5, lane=threadIdx.x&31;
    float q00=pgk_w[0*Dd+ebase+lane], q01=pgk_w[0*Dd+ebase+lane+32];
    float q10=pgk_w[1*Dd+ebase+lane], q11=pgk_w[1*Dd+ebase+lane+32];
    float q20=pgk_w[2*Dd+ebase+lane], q21=pgk_w[2*Dd+ebase+lane+32];
    for(int rr=wid*8; rr<wid*8+8; rr++){
        float w0=shw[lane][rr], w1=shw[lane+32][rr];
        float a=w0*q00+w1*q01, b=w0*q10+w1*q11, c=w0*q20+w1*q21;
        a=warp_sum(a); b=warp_sum(b); c=warp_sum(c);
        if(!lane){
            atomicAdd(&g_wpk[0][j][dt*64+rr],a);
            atomicAdd(&g_wpk[1][j][dt*64+rr],b);
            atomicAdd(&g_wpk[2][j][dt*64+rr],c);
        }
    }
}

// ======== kernel 4: FUSED row stats + attention dots + kl (single feats pass) ========
// 768 blocks: (m, b, s-chunk of 32)
__global__ void k_rowstats(const float* __restrict__ feats){
    __shared__ float4 sw4[7][D4];
    __shared__ float skl[8];
    int blk=blockIdx.x;
    int m  = blk/256;
    int b  = (blk/8)%Bb;
    int sc = blk%8;
    int i0=(m==0)?1:0, i1=(m==2)?1:2;
    for(int d=threadIdx.x; d<D4; d+=256){
        sw4[0][d]=((const float4*)g_wmu[m])[d];
        sw4[1][d]=((const float4*)g_wlv[m])[d];
        sw4[2][d]=((const float4*)g_wpq[m])[d];
        sw4[3][d]=((const float4*)g_wpk[i0][m])[d];
        sw4[4][d]=((const float4*)g_wpk[i1][m])[d];
        sw4[5][d]=((const float4*)g_qkvec[i0][m][b])[d];
        sw4[6][d]=((const float4*)g_qkvec[i1][m][b])[d];
    }
    __syncthreads();
    int wid=threadIdx.x>>5, lane=threadIdx.x&31;
    float qb0=g_qbk[i0][m][b], qb1=g_qbk[i1][m][b];
    float klacc=0.f;
    const float* base = feats + ((size_t)m*Bb+b)*Ss*Dd;
    int s0 = sc*32 + wid*4;
    for(int t=0;t<4;t+=2){
        int s = s0+t;
        const float4* f0=(const float4*)(base + (size_t)s*Dd);
        const float4* f1=f0+D4;
        float a0=0,a1=0,a2=0,a3=0,a4=0,a5=0,a6=0;
        float c0=0,c1=0,c2=0,c3=0,c4=0,c5=0,c6=0;
        for(int d=lane; d<D4; d+=32){
            float4 x0=f0[d], x1=f1[d];
            a0+=dot4(x0,sw4[0][d]); c0+=dot4(x1,sw4[0][d]);
            a1+=dot4(x0,sw4[1][d]); c1+=dot4(x1,sw4[1][d]);
            a2+=dot4(x0,sw4[2][d]); c2+=dot4(x1,sw4[2][d]);
            a3+=dot4(x0,sw4[3][d]); c3+=dot4(x1,sw4[3][d]);
            a4+=dot4(x0,sw4[4][d]); c4+=dot4(x1,sw4[4][d]);
            a5+=dot4(x0,sw4[5][d]); c5+=dot4(x1,sw4[5][d]);
            a6+=dot4(x0,sw4[6][d]); c6+=dot4(x1,sw4[6][d]);
        }
        a0=warp_sum(a0); a1=warp_sum(a1); a2=warp_sum(a2); a3=warp_sum(a3);
        a4=warp_sum(a4); a5=warp_sum(a5); a6=warp_sum(a6);
        c0=warp_sum(c0); c1=warp_sum(c1); c2=warp_sum(c2); c3=warp_sum(c3);
        c4=warp_sum(c4); c5=warp_sum(c5); c6=warp_sum(c6);
        if(!lane){
            float mu=a0+g_cmu[m], lv=a1+g_clv[m];
            g_mu[m][b][s]=mu; g_lv[m][b][s]=lv;
            g_pqb[m][b][s]=a2+g_cpq[m];
            g_kd[i0][m][b][s]=a3+g_cpk[i0][m];
            g_kd[i1][m][b][s]=a4+g_cpk[i1][m];
            g_dotA[i0][m][b][s]=a5+qb0;
            g_dotA[i1][m][b][s]=a6+qb1;
            klacc += 1.f + lv - mu*mu - expf(lv);
            float mu2=c0+g_cmu[m], lv2=c1+g_clv[m];
            g_mu[m][b][s+1]=mu2; g_lv[m][b][s+1]=lv2;
            g_pqb[m][b][s+1]=c2+g_cpq[m];
            g_kd[i0][m][b][s+1]=c3+g_cpk[i0][m];
            g_kd[i1][m][b][s+1]=c4+g_cpk[i1][m];
            g_dotA[i0][m][b][s+1]=c5+qb0;
            g_dotA[i1][m][b][s+1]=c6+qb1;
            klacc += 1.f + lv2 - mu2*mu2 - expf(lv2);
        }
    }
    if(!lane) skl[wid]=klacc;
    __syncthreads();
    if(threadIdx.x==0){
        float t=0.f;
        #pragma unroll
        for(int w=0;w<8;w++) t+=skl[w];
        atomicAdd(&g_kl, t);
    }
}

// ======== kernel 5: gates + softmax + weighted feats sums (288 blocks) ========
__global__ void k_attn2(const float* __restrict__ feats, const float* __restrict__ eps,
                        const float* __restrict__ dyn){
    __shared__ float w0[Ss], w1[Ss];
    __shared__ float sred[8];
    __shared__ float spq0, spq1, sscal;
    int blk=blockIdx.x;
    int j  = blk/96;
    int b  = (blk/3)%Bb;
    int dc = blk%3;
    int i0=(j==0)?1:0, i1=(j==2)?1:2;
    int cnt0=(j<i0)? j : j-1;
    int cnt1=(j<i1)? j : j-1;
    int k=threadIdx.x;
    int wid=k>>5, lane=k&31;
    float dynv=dyn[0];
    // gates
    float mu0=g_mu[i0][b][k], lv0=g_lv[i0][b][k];
    float e0 = eps[(((size_t)i0*(Mm-1)+cnt0)*Bb + b)*Ss + k];
    float gk0 = sigmoidf(mu0 + dynv*expf(0.5f*lv0)*e0);
    float pk0 = sigmoidf(g_kd[i0][j][b][k]) * gk0;
    float mu1=g_mu[i1][b][k], lv1=g_lv[i1][b][k];
    float e1 = eps[(((size_t)i1*(Mm-1)+cnt1)*Bb + b)*Ss + k];
    float gk1 = sigmoidf(mu1 + dynv*expf(0.5f*lv1)*e1);
    float pk1 = sigmoidf(g_kd[i1][j][b][k]) * gk1;
    if(k==0){
        spq0 = sigmoidf(g_pqb[i0][b][0]) * gk0;
        spq1 = sigmoidf(g_pqb[i1][b][0]) * gk1;
    }
    __syncthreads();
    float l0 = g_dotA[i0][j][b][k]*SCALE*spq0*pk0;
    float l1 = g_dotA[i1][j][b][k]*SCALE*spq1*pk1;
    // softmax pair 0
    {
        float mx=l0;
        #pragma unroll
        for(int o=16;o>0;o>>=1) mx=fmaxf(mx,__shfl_xor_sync(0xffffffffu,mx,o));
        if(!lane) sred[wid]=mx;
        __syncthreads();
        if(threadIdx.x==0){ float t=sred[0];
            #pragma unroll
            for(int w=1;w<8;w++) t=fmaxf(t,sred[w]); sscal=t; }
        __syncthreads();
        float ex=expf(l0-sscal);
        float sm=ex;
        #pragma unroll
        for(int o=16;o>0;o>>=1) sm+=__shfl_xor_sync(0xffffffffu,sm,o);
        if(!lane) sred[wid]=sm;
        __syncthreads();
        if(threadIdx.x==0){ float t=0.f;
            #pragma unroll
            for(int w=0;w<8;w++) t+=sred[w]; sscal=t; }
        __syncthreads();
        w0[k]=ex/sscal;
        __syncthreads();
    }
    // softmax pair 1
    {
        float mx=l1;
        #pragma unroll
        for(int o=16;o>0;o>>=1) mx=fmaxf(mx,__shfl_xor_sync(0xffffffffu,mx,o));
        if(!lane) sred[wid]=mx;
        __syncthreads();
        if(threadIdx.x==0){ float t=sred[0];
            #pragma unroll
            for(int w=1;w<8;w++) t=fmaxf(t,sred[w]); sscal=t; }
        __syncthreads();
        float ex=expf(l1-sscal);
        float sm=ex;
        #pragma unroll
        for(int o=16;o>0;o>>=1) sm+=__shfl_xor_sync(0xffffffffu,sm,o);
        if(!lane) sred[wid]=sm;
        __syncthreads();
        if(threadIdx.x==0){ float t=0.f;
            #pragma unroll
            for(int w=0;w<8;w++) t+=sred[w]; sscal=t; }
        __syncthreads();
        w1[k]=ex/sscal;
        __syncthreads();
    }
    // weighted sum over this block's 256-d chunk
    int d = dc*256 + threadIdx.x;
    const float* ftile = feats + (((size_t)j*Bb+b)*Ss)*Dd;
    float acc0=0.f, acc1=0.f;
    #pragma unroll 8
    for(int kk=0;kk<Ss;kk++){
        float f = ftile[(size_t)kk*Dd + d];
        acc0 += w0[kk]*f; acc1 += w1[kk]*f;
    }
    g_wf[i0][j][b][d]=acc0;
    g_wf[i1][j][b][d]=acc1;
}

// ======== kernel 6: agg += wf @ Wv (864 single-tile blocks) ========
__global__ void k_agg(const float* __restrict__ Wv, const float* __restrict__ bv){
    __shared__ float sh[32][64];
    __shared__ float shw[64][64];
    int blk=blockIdx.x;
    int i = blk/288; int rem=blk%288;
    int et = rem/24; int rem2=rem%24;
    int jj = rem2/12; int kc = rem2%12;
    int j0=(i==0)?1:0, j1=(i==2)?1:2;
    int j = jj? j1 : j0;
    int tx=threadIdx.x&63, ty=threadIdx.x>>6;
    int e=et*64+tx;
    int dbase=kc*64;
    for(int q=threadIdx.x;q<512;q+=256){
        int bb=q>>4, dd4=q&15;
        ((float4*)sh[bb])[dd4] = ((const float4*)(&g_wf[i][j][bb][dbase]))[dd4];
    }
    for(int q=threadIdx.x;q<1024;q+=256){
        int rr=q>>4, cc=q&15;
        ((float4*)shw[rr])[cc] =
            ((const float4*)(Wv + ((size_t)j*Dd + dbase+rr)*Dd + et*64))[cc];
    }
    __syncthreads();
    float acc[8];
    float binit = (kc==0)? bv[j*Dd+e] : 0.f;
    #pragma unroll
    for(int r=0;r<8;r++) acc[r]=binit;
    #pragma unroll 8
    for(int d=0;d<64;d++){
        float w=shw[d][tx];
        #pragma unroll
        for(int r=0;r<8;r++) acc[r]+=sh[ty+r*4][d]*w;
    }
    #pragma unroll
    for(int r=0;r<8;r++) atomicAdd(&g_agg[i][ty+r*4][e], acc[r]);
}

// ======== kernel 7: E/G accumulation (1296 single-tile blocks) ========
__global__ void k_eg(const float* __restrict__ WE, const float* __restrict__ WEb,
                     const float* __restrict__ Wh, const float* __restrict__ Whb,
                     const float* __restrict__ Wqc, const float* __restrict__ Wqcb){
    __shared__ float sh[32][64];
    __shared__ float shw[64][64];
    int blk=blockIdx.x;
    int i = blk/432; int rem=blk%432;
    int et = rem/36; int rem2=rem%36;
    int seg = rem2/12; int kc = rem2%12;
    int tx=threadIdx.x&63, ty=threadIdx.x>>6;
    int e=et*64+tx;
    int dbase=kc*64;
    const float* W  = (seg==0)? WE : (seg==1)? Wh : Wqc;
    const float* src = (seg==2)? &g_Q0[i][0][0] : &g_agg[i][0][0];
    float* dst = (seg==0)? &g_E[i][0][0] : &g_G[i][0][0];
    for(int q=threadIdx.x;q<512;q+=256){
        int bb=q>>4, dd4=q&15;
        ((float4*)sh[bb])[dd4] = ((const float4*)(src + (size_t)bb*Dd + dbase))[dd4];
    }
    for(int q=threadIdx.x;q<1024;q+=256){
        int rr=q>>4, cc=q&15;
        ((float4*)shw[rr])[cc] =
            ((const float4*)(W + ((size_t)i*Dd + dbase+rr)*Dd + et*64))[cc];
    }
    __syncthreads();
    float binit = 0.f;
    if(kc==0){
        if(seg==0) binit = WEb[i*Dd+e];
        else if(seg==1) binit = Whb[i*Dd+e]+Wqcb[i*Dd+e];
    }
    float acc[8];
    #pragma unroll
    for(int r=0;r<8;r++) acc[r]=binit;
    #pragma unroll 8
    for(int d=0;d<64;d++){
        float w=shw[d][tx];
        #pragma unroll
        for(int r=0;r<8;r++) acc[r]+=sh[ty+r*4][d]*w;
    }
    #pragma unroll
    for(int r=0;r<8;r++) atomicAdd(dst + (size_t)(ty+r*4)*Dd + e, acc[r]);
}

__device__ __forceinline__ float block_sum256(float v, float* sred){
    v = warp_sum(v);
    int wid=threadIdx.x>>5, lane=threadIdx.x&31;
    if(!lane) sred[wid]=v;
    __syncthreads();
    float t = (threadIdx.x<8)? sred[threadIdx.x] : 0.f;
    if(threadIdx.x<32){
        #pragma unroll
        for(int o=16;o>0;o>>=1) t += __shfl_xor_sync(0xffffffffu,t,o);
        if(threadIdx.x==0) sred[0]=t;
    }
    __syncthreads();
    float r = sred[0];
    __syncthreads();
    return r;
}

// ======== kernel 8: C = LN(relu(E))*LN(relu(G))  +  dout bias init ========
__global__ void k_lnprod(const float* __restrict__ lnEg, const float* __restrict__ lnEb,
                         const float* __restrict__ lnGg, const float* __restrict__ lnGb,
                         const float* __restrict__ out_b, float* __restrict__ dout){
    if(blockIdx.x >= Mm*Bb){
        int b = blockIdx.x - Mm*Bb;
        #pragma unroll
        for(int t=0;t<4;t++)
            dout[(size_t)b*Hh + t*256 + threadIdx.x] = out_b[t*256 + threadIdx.x];
        return;
    }
    __shared__ float sred[8];
    int i = blockIdx.x/Bb, b = blockIdx.x%Bb;
    float se=0.f, se2=0.f, sg=0.f, sg2=0.f;
    for(int d=threadIdx.x; d<Dd; d+=256){
        float ev=fmaxf(g_E[i][b][d],0.f), gv=fmaxf(g_G[i][b][d],0.f);
        se+=ev; se2+=ev*ev; sg+=gv; sg2+=gv*gv;
    }
    se  = block_sum256(se , sred);
    se2 = block_sum256(se2, sred);
    sg  = block_sum256(sg , sred);
    sg2 = block_sum256(sg2, sred);
    float mE = se/(float)Dd,  vE = se2/(float)Dd - mE*mE;
    float mG = sg/(float)Dd,  vG = sg2/(float)Dd - mG*mG;
    float rE = rsqrtf(vE + LNEPS), rG = rsqrtf(vG + LNEPS);
    for(int d=threadIdx.x; d<Dd; d+=256){
        float nE = (fmaxf(g_E[i][b][d],0.f)-mE)*rE*lnEg[i*Dd+d] + lnEb[i*Dd+d];
        float nG = (fmaxf(g_G[i][b][d],0.f)-mG)*rG*lnGg[i*Dd+d] + lnGb[i*Dd+d];
        g_C[i][b][d] = nE*nG;
    }
}

// ======== kernel 9: out += fused @ out_w (576 single-tile blocks) + kl ========
__global__ void k_out(const float* __restrict__ out_w, float* __restrict__ dout,
                      int write_kl){
    int blk=blockIdx.x;
    if(blk>=576){
        if(threadIdx.x==0 && write_kl) dout[Bb*Hh] = -0.5f*(float)(Mm-1)*g_kl;
        return;
    }
    __shared__ float sf[32][64];
    __shared__ float shw[64][64];
    int ht = blk/36;
    int kc = blk%36;
    int c0 = kc*64;
    int ii = c0/Dd; int dd = c0%Dd;
    int tx=threadIdx.x&63, ty=threadIdx.x>>6;
    int h = ht*64 + tx;
    for(int q=threadIdx.x;q<512;q+=256){
        int bb=q>>4, dd4=q&15;
        ((float4*)sf[bb])[dd4] = ((const float4*)(&g_C[ii][bb][dd]))[dd4];
    }
    for(int q=threadIdx.x;q<1024;q+=256){
        int rr=q>>4, cc=q&15;
        ((float4*)shw[rr])[cc] =
            ((const float4*)(out_w + ((size_t)(c0+rr))*Hh + ht*64))[cc];
    }
    __syncthreads();
    float acc[8];
    #pragma unroll
    for(int r=0;r<8;r++) acc[r]=0.f;
    #pragma unroll 8
    for(int d=0;d<64;d++){
        float w=shw[d][tx];
        #pragma unroll
        for(int r=0;r<8;r++) acc[r]+=sf[ty+r*4][d]*w;
    }
    #pragma unroll
    for(int r=0;r<8;r++) atomicAdd(&dout[(size_t)(ty+r*4)*Hh + h], acc[r]);
}

extern "C" void kernel_launch(void* const* d_in, const int* in_sizes, int n_in,
                              void* d_out, int out_size) {
    const float* feats = (const float*)d_in[0];
    const float* Wq    = (const float*)d_in[1];
    const float* bq    = (const float*)d_in[2];
    const float* Wk    = (const float*)d_in[3];
    const float* bk    = (const float*)d_in[4];
    const float* Wv    = (const float*)d_in[5];
    const float* bv    = (const float*)d_in[6];
    const float* pgq_w = (const float*)d_in[7];
    const float* pgq_b = (const float*)d_in[8];
    const float* pgk_w = (const float*)d_in[9];
    const float* pgk_b = (const float*)d_in[10];
    const float* mu_w  = (const float*)d_in[11];
    const float* mu_b  = (const float*)d_in[12];
    const float* lv_w  = (const float*)d_in[13];
    const float* lv_b  = (const float*)d_in[14];
    const float* dyn   = (const float*)d_in[15];
    const float* WE_w  = (const float*)d_in[16];
    const float* WE_b  = (const float*)d_in[17];
    const float* Wh_w  = (const float*)d_in[18];
    const float* Wh_b  = (const float*)d_in[19];
    const float* Wqc_w = (const float*)d_in[20];
    const float* Wqc_b = (const float*)d_in[21];
    const float* lnE_g = (const float*)d_in[22];
    const float* lnE_b = (const float*)d_in[23];
    const float* lnG_g = (const float*)d_in[24];
    const float* lnG_b = (const float*)d_in[25];
    const float* out_w = (const float*)d_in[26];
    const float* out_b = (const float*)d_in[27];
    const float* eps   = (const float*)d_in[28];
    float* dout = (float*)d_out;

    k_init<<<161,256>>>(bq, bk, mu_w, mu_b, lv_w, lv_b, pgq_w, pgq_b, pgk_w, pgk_b);
    k_q0<<<432,256>>>(feats, Wq, bq, mu_w, lv_w, pgq_w);
    k_qkvec<<<438,256>>>(Wk, bk, pgk_w);
    k_rowstats<<<768,256>>>(feats);
    k_attn2<<<288,256>>>(feats, eps, dyn);
    k_agg<<<864,256>>>(Wv, bv);
    k_eg<<<1296,256>>>(WE_w, WE_b, Wh_w, Wh_b, Wqc_w, Wqc_b);
    k_lnprod<<<128,256>>>(lnE_g, lnE_b, lnG_g, lnG_b, out_b, dout);
    k_out<<<577,256>>>(out_w, dout, (out_size > Bb*Hh) ? 1 : 0);
}